// round 9
// baseline (speedup 1.0000x reference)
#include <cuda_runtime.h>
#include <cuda_fp16.h>
#include <math_constants.h>
#include <cstdint>

// ---------------------------------------------------------------------------
// Problem constants
// ---------------------------------------------------------------------------
#define B_DIM 4
#define T_DIM 2048
#define C_DIM 1024
#define H_DIM 16
#define D_DIM 64
#define M_ROWS (B_DIM * T_DIM)       // 8192
#define N_QKV  (3 * C_DIM)           // 3072

// ---------------------------------------------------------------------------
// Device scratch (allocation-free rule)
// ---------------------------------------------------------------------------
__device__ __half g_qkvh[(size_t)M_ROWS * N_QKV];   // qkv fp16 hi
__device__ __half g_qkvl[(size_t)M_ROWS * N_QKV];   // qkv fp16 lo (Q cols only)
__device__ __half g_xh[(size_t)M_ROWS * C_DIM];
__device__ __half g_xl[(size_t)M_ROWS * C_DIM];
__device__ __half g_wt[(size_t)N_QKV * C_DIM];      // w_attn^T fp16 [3072][1024]
__device__ __half g_wpt[(size_t)C_DIM * C_DIM];     // w_proj^T fp16 [1024][1024]
__device__ __half g_ath[(size_t)M_ROWS * C_DIM];
__device__ __half g_atl[(size_t)M_ROWS * C_DIM];

// ---------------------------------------------------------------------------
// Helpers
// ---------------------------------------------------------------------------
__device__ __forceinline__ uint32_t smem_u32(const void* p) {
    uint32_t a;
    asm("{ .reg .u64 t; cvta.to.shared.u64 t, %1; cvt.u32.u64 %0, t; }"
        : "=r"(a) : "l"(p));
    return a;
}

__device__ __forceinline__ void cp16(uint32_t dst, const void* src) {
    asm volatile("cp.async.cg.shared.global [%0], [%1], 16;"
                 :: "r"(dst), "l"(src));
}
#define CP_COMMIT() asm volatile("cp.async.commit_group;" ::: "memory")
#define CP_WAIT(n)  asm volatile("cp.async.wait_group %0;" :: "n"(n) : "memory")

__device__ __forceinline__ void ldsm4(uint32_t* r, uint32_t addr) {
    asm volatile("ldmatrix.sync.aligned.m8n8.x4.shared.b16 {%0,%1,%2,%3}, [%4];"
                 : "=r"(r[0]), "=r"(r[1]), "=r"(r[2]), "=r"(r[3]) : "r"(addr));
}

__device__ __forceinline__ void ldsm4t(uint32_t* r, uint32_t addr) {
    asm volatile("ldmatrix.sync.aligned.m8n8.x4.trans.shared.b16 {%0,%1,%2,%3}, [%4];"
                 : "=r"(r[0]), "=r"(r[1]), "=r"(r[2]), "=r"(r[3]) : "r"(addr));
}

__device__ __forceinline__ void mma16816(float* c, const uint32_t* a,
                                         const uint32_t* b) {
    asm volatile(
        "mma.sync.aligned.m16n8k16.row.col.f32.f16.f16.f32 "
        "{%0,%1,%2,%3}, {%4,%5,%6,%7}, {%8,%9}, {%0,%1,%2,%3};"
        : "+f"(c[0]), "+f"(c[1]), "+f"(c[2]), "+f"(c[3])
        : "r"(a[0]), "r"(a[1]), "r"(a[2]), "r"(a[3]), "r"(b[0]), "r"(b[1]));
}

// Fast exp on the FMA pipe (no MUFU). Valid for x <= 0; err ~3e-6 rel.
__device__ __forceinline__ float fexp(float x) {
    const float LOG2E = 1.4426950408889634f;
    const float MAGIC = 12582912.0f;          // 1.5 * 2^23
    x = fmaxf(x, -80.0f);
    float t = fmaf(x, LOG2E, MAGIC);
    int   i = __float_as_int(t);
    float n = t - MAGIC;
    float f = fmaf(x, LOG2E, -n);             // f in [-0.5, 0.5]
    float p = 0.0013333558f;
    p = fmaf(p, f, 0.0096181291f);
    p = fmaf(p, f, 0.0555041086f);
    p = fmaf(p, f, 0.2402265069f);
    p = fmaf(p, f, 0.6931471806f);
    p = fmaf(p, f, 1.0f);
    return __int_as_float(__float_as_int(p) + (i << 23));
}

// Split a pair of floats into packed fp16 hi / lo uint32 fragments
__device__ __forceinline__ void split2h(float x, float y, uint32_t& h, uint32_t& l) {
    __half hx = __float2half(x);
    __half hy = __float2half(y);
    __half lx = __float2half(x - __half2float(hx));
    __half ly = __float2half(y - __half2float(hy));
    __half2 hp(hx, hy), lp(lx, ly);
    h = *reinterpret_cast<uint32_t*>(&hp);
    l = *reinterpret_cast<uint32_t*>(&lp);
}

// ---------------------------------------------------------------------------
// Prep kernels
// ---------------------------------------------------------------------------
__global__ void k_split(const float* __restrict__ in,
                        __half* __restrict__ hi,
                        __half* __restrict__ lo, int n)
{
    int i = (blockIdx.x * blockDim.x + threadIdx.x) * 4;
    if (i >= n) return;
    float4 v = *(const float4*)(in + i);
    float f[4] = {v.x, v.y, v.z, v.w};
    __half h[4], l[4];
#pragma unroll
    for (int j = 0; j < 4; ++j) {
        h[j] = __float2half(f[j]);
        l[j] = __float2half(f[j] - __half2float(h[j]));
    }
    *(__half2*)(hi + i)     = __half2(h[0], h[1]);
    *(__half2*)(hi + i + 2) = __half2(h[2], h[3]);
    *(__half2*)(lo + i)     = __half2(l[0], l[1]);
    *(__half2*)(lo + i + 2) = __half2(l[2], l[3]);
}

// W[K][N] row-major -> T[N][K] fp16 (single)
__global__ void k_transpose_half(const float* __restrict__ W,
                                 __half* __restrict__ T, int K, int N)
{
    __shared__ float tile[32][33];
    const int k0 = blockIdx.y * 32;
    const int n0 = blockIdx.x * 32;
    const int tx = threadIdx.x;
    const int ty = threadIdx.y;
#pragma unroll
    for (int r = 0; r < 4; ++r)
        tile[ty + r * 8][tx] = W[(size_t)(k0 + ty + r * 8) * N + n0 + tx];
    __syncthreads();
#pragma unroll
    for (int r = 0; r < 4; ++r) {
        float v = tile[tx][ty + r * 8];
        T[(size_t)(n0 + ty + r * 8) * K + k0 + tx] = __float2half(v);
    }
}

// ---------------------------------------------------------------------------
// HMMA GEMM: C = A @ Bt^T + bias.  A = fp16 hi/lo 2-product, B = fp16 single.
// 128x256 CTA tile, 256 threads = 8 warps of 64x64 (2 M x 4 N).
// BK=32, 3-stage cp.async ring, one barrier per chunk, 1 CTA/SM.
// Fragment reuse: 12 ldsm -> 64 MMAs per ks (96 B smem per MMA).
// ---------------------------------------------------------------------------
#define BKC  32
#define LDSB 80                       // smem row stride bytes (32 fp16 = 64B + pad)
#define A_T  (128 * LDSB)             // 10240 per A operand tile (hi or lo)
#define B_T  (256 * LDSB)             // 20480 for B tile
#define STG  (2 * A_T + B_T)          // 40960 per stage
#define NSTG 3
#define GEMM_SMEM (NSTG * STG)        // 122880

template<bool SPLIT_OUT>
__global__ void __launch_bounds__(256, 1)
gemm_mma(const __half* __restrict__ Ah, const __half* __restrict__ Al,
         const __half* __restrict__ Bf,
         const float* __restrict__ bias, float* __restrict__ C,
         __half* __restrict__ Ch, __half* __restrict__ Cl,
         int N, int K)
{
    extern __shared__ char sm[];
    const uint32_t sbase = smem_u32(sm);

    const int tid  = threadIdx.x;
    const int lane = tid & 31;
    const int wid  = tid >> 5;
    const int m0 = blockIdx.y * 128;
    const int n0 = blockIdx.x * 256;
    const int wm = (wid & 1) * 64;        // 2 warps along M
    const int wn = (wid >> 1) * 64;       // 4 warps along N

    float acc[4][8][4];
#pragma unroll
    for (int i = 0; i < 4; ++i)
#pragma unroll
        for (int j = 0; j < 8; ++j)
#pragma unroll
            for (int k = 0; k < 4; ++k) acc[i][j][k] = 0.0f;

    // loader: A tiles 512 x 16B slots (2/thread each), B tile 1024 slots (4/thread)
    const int r0 = tid >> 2, c0 = tid & 3;
    const __half* pAh0 = Ah + (size_t)(m0 + r0) * K + c0 * 8;
    const __half* pAh1 = Ah + (size_t)(m0 + r0 + 64) * K + c0 * 8;
    const __half* pAl0 = Al + (size_t)(m0 + r0) * K + c0 * 8;
    const __half* pAl1 = Al + (size_t)(m0 + r0 + 64) * K + c0 * 8;
    const __half* pB0  = Bf + (size_t)(n0 + r0) * K + c0 * 8;
    const __half* pB1  = Bf + (size_t)(n0 + r0 + 64) * K + c0 * 8;
    const __half* pB2  = Bf + (size_t)(n0 + r0 + 128) * K + c0 * 8;
    const __half* pB3  = Bf + (size_t)(n0 + r0 + 192) * K + c0 * 8;
    const uint32_t d0 = (uint32_t)r0 * LDSB + (uint32_t)c0 * 16;
    const uint32_t d1 = d0 + 64 * LDSB;
    const uint32_t d2 = d0 + 128 * LDSB;
    const uint32_t d3 = d0 + 192 * LDSB;

    auto load_chunk = [&](int c, int buf) {
        const int koff = c * BKC;
        const uint32_t db = sbase + buf * STG;
        cp16(db + 0 * A_T + d0, pAh0 + koff);
        cp16(db + 0 * A_T + d1, pAh1 + koff);
        cp16(db + 1 * A_T + d0, pAl0 + koff);
        cp16(db + 1 * A_T + d1, pAl1 + koff);
        cp16(db + 2 * A_T + d0, pB0 + koff);
        cp16(db + 2 * A_T + d1, pB1 + koff);
        cp16(db + 2 * A_T + d2, pB2 + koff);
        cp16(db + 2 * A_T + d3, pB3 + koff);
        CP_COMMIT();
    };

    const int NC = K / BKC;
    load_chunk(0, 0);
    load_chunk(1, 1);

    int buf = 0;
    for (int c = 0; c < NC; ++c) {
        if (c + 1 < NC) { CP_WAIT(1); } else { CP_WAIT(0); }
        __syncthreads();
        if (c + 2 < NC) {
            int nb = buf + 2; if (nb >= NSTG) nb -= NSTG;
            load_chunk(c + 2, nb);
        }

        const uint32_t tb = sbase + buf * STG;
#pragma unroll
        for (int ks = 0; ks < 2; ++ks) {
            uint32_t ah[4][4], al[4][4];
#pragma unroll
            for (int mi = 0; mi < 4; ++mi) {
                uint32_t off = (uint32_t)(wm + mi * 16 + (lane & 15)) * LDSB
                             + ks * 32 + (lane >> 4) * 16;
                ldsm4(ah[mi], tb + 0 * A_T + off);
                ldsm4(al[mi], tb + 1 * A_T + off);
            }
#pragma unroll
            for (int np = 0; np < 4; ++np) {
                uint32_t bf[4];
                uint32_t off = (uint32_t)(wn + np * 16 + (lane & 7)
                             + ((lane >> 4) & 1) * 8) * LDSB
                             + ks * 32 + ((lane >> 3) & 1) * 16;
                ldsm4(bf, tb + 2 * A_T + off);
#pragma unroll
                for (int mi = 0; mi < 4; ++mi)
#pragma unroll
                    for (int nj = 0; nj < 2; ++nj) {
                        float* a = acc[mi][2 * np + nj];
                        mma16816(a, ah[mi], &bf[nj * 2]);
                        mma16816(a, al[mi], &bf[nj * 2]);
                    }
            }
        }
        if (++buf >= NSTG) buf -= NSTG;
    }

#pragma unroll
    for (int mi = 0; mi < 4; ++mi) {
        const int row = m0 + wm + mi * 16 + (lane >> 2);
#pragma unroll
        for (int ni = 0; ni < 8; ++ni) {
            const int col = n0 + wn + ni * 8 + (lane & 3) * 2;
            const float b0v = bias[col];
            const float b1v = bias[col + 1];
            const float v0x = acc[mi][ni][0] + b0v;
            const float v0y = acc[mi][ni][1] + b1v;
            const float v1x = acc[mi][ni][2] + b0v;
            const float v1y = acc[mi][ni][3] + b1v;
            if (SPLIT_OUT) {
                uint32_t h0, l0, h1, l1;
                split2h(v0x, v0y, h0, l0);
                split2h(v1x, v1y, h1, l1);
                const size_t o0 = (size_t)row * N + col;
                const size_t o1 = (size_t)(row + 8) * N + col;
                *(uint32_t*)(Ch + o0) = h0;
                *(uint32_t*)(Ch + o1) = h1;
                if (col < C_DIM) {          // lo only ever read for Q columns
                    *(uint32_t*)(Cl + o0) = l0;
                    *(uint32_t*)(Cl + o1) = l1;
                }
            } else {
                float2 v0, v1;
                v0.x = v0x; v0.y = v0y;
                v1.x = v1x; v1.y = v1y;
                *(float2*)(C + (size_t)row * N + col)       = v0;
                *(float2*)(C + (size_t)(row + 8) * N + col) = v1;
            }
        }
    }
}

// ---------------------------------------------------------------------------
// HMMA causal flash attention. CTA: 128 q-rows x one (b,h). 8 warps x 16 rows.
// fp16 2-product: Q (hi/lo) x K (hi);  P (hi/lo) x V (hi).
// 3-stage K/V ring, one barrier per tile, 2 CTAs/SM.  (unchanged from R8)
// ---------------------------------------------------------------------------
#define FA_BQ   128
#define FA_BC   64
#define FA_LDB  144
#define FA_QH   0
#define FA_QL   (FA_BQ * FA_LDB)
#define FA_BUF  (2 * FA_BQ * FA_LDB)     // 36864: Q hi+lo
#define FA_TILE (FA_BC * FA_LDB)         // 9216
#define FA_BUFSZ (2 * FA_TILE)           // 18432 (Kh, Vh)
#define FA_NSTG 3
#define FA_SMEM (FA_BUF + FA_NSTG * FA_BUFSZ)  // 92160
#define NEG_BIG (-1e30f)

__global__ void __launch_bounds__(256, 2)
flash_mma(const __half* __restrict__ qh,
          const __half* __restrict__ ql,
          __half* __restrict__ ath,
          __half* __restrict__ atl)
{
    extern __shared__ char fsm[];
    const uint32_t sb = smem_u32(fsm);

    const int tid  = threadIdx.x;
    const int lane = tid & 31;
    const int wid  = tid >> 5;
    const int b = blockIdx.x >> 4;
    const int h = blockIdx.x & 15;
    const int yy = (int)gridDim.y - 1 - (int)blockIdx.y;   // heavy tiles first
    const int q0 = yy * FA_BQ;
    const int NT = 2 * (yy + 1);
    const int bT = b * T_DIM;
    const int hoff = h * D_DIM;

    auto load_tile = [&](int t, int bufi) {
        const int k0 = t * FA_BC;
        const int row = tid >> 2;
        const int ch2 = (tid & 3) * 2;
        const size_t rb = (size_t)(bT + k0 + row) * N_QKV + hoff;
        const uint32_t tb = sb + FA_BUF + bufi * FA_BUFSZ;
        const uint32_t d = tb + row * FA_LDB + ch2 * 16;
        const __half* skh = qh + rb + C_DIM;
        const __half* svh = qh + rb + 2 * C_DIM;
        cp16(d + 0 * FA_TILE,      skh + ch2 * 8);
        cp16(d + 0 * FA_TILE + 16, skh + ch2 * 8 + 8);
        cp16(d + 1 * FA_TILE,      svh + ch2 * 8);
        cp16(d + 1 * FA_TILE + 16, svh + ch2 * 8 + 8);
        CP_COMMIT();
    };

    // ---- issue Q tile load, then prefetch K/V tiles 0 & 1 ----
#pragma unroll
    for (int i = 0; i < 8; ++i) {
        int idx = tid + i * 256;
        int arr = idx >> 10;
        int wi  = idx & 1023;
        int row = wi >> 3;
        int ch  = wi & 7;
        const __half* src = (arr ? ql : qh)
            + (size_t)(bT + q0 + row) * N_QKV + hoff + ch * 8;
        cp16(sb + arr * (FA_BQ * FA_LDB) + row * FA_LDB + ch * 16, src);
    }
    CP_COMMIT();
    load_tile(0, 0);
    load_tile(1, 1);          // NT >= 2 always

    CP_WAIT(2);               // Q done; K/V tiles may still be in flight
    __syncthreads();

    uint32_t qfh[4][4], qfl[4][4];
#pragma unroll
    for (int ks = 0; ks < 4; ++ks) {
        uint32_t off = (uint32_t)(wid * 16 + (lane & 15)) * FA_LDB
                     + ks * 32 + (lane >> 4) * 16;
        ldsm4(qfh[ks], sb + FA_QH + off);
        ldsm4(qfl[ks], sb + FA_QL + off);
    }

    float o[8][4];
#pragma unroll
    for (int i = 0; i < 8; ++i)
#pragma unroll
        for (int j = 0; j < 4; ++j) o[i][j] = 0.0f;
    float m0 = NEG_BIG, m1 = NEG_BIG, l0 = 0.0f, l1 = 0.0f;
    const int qr  = q0 + wid * 16;
    const int qp0 = qr + (lane >> 2);
    const int qp1 = qp0 + 8;

    int buf = 0;
    for (int t = 0; t < NT; ++t) {
        if (t + 1 < NT) { CP_WAIT(1); } else { CP_WAIT(0); }
        __syncthreads();
        if (t + 2 < NT) {
            int nb = buf + 2; if (nb >= FA_NSTG) nb -= FA_NSTG;
            load_tile(t + 2, nb);
        }

        const int k0 = t * FA_BC;
        if (k0 <= qr + 15) {
            const uint32_t tb = sb + FA_BUF + buf * FA_BUFSZ;

            float s[8][4];
#pragma unroll
            for (int i = 0; i < 8; ++i)
#pragma unroll
                for (int j = 0; j < 4; ++j) s[i][j] = 0.0f;

#pragma unroll
            for (int ks = 0; ks < 4; ++ks) {
                uint32_t kh[4][4];
#pragma unroll
                for (int np = 0; np < 4; ++np) {
                    uint32_t off = (uint32_t)(np * 16 + (lane & 7)
                                 + ((lane >> 4) & 1) * 8) * FA_LDB
                                 + ks * 32 + ((lane >> 3) & 1) * 16;
                    ldsm4(kh[np], tb + 0 * FA_TILE + off);
                }
#pragma unroll
                for (int ni = 0; ni < 8; ++ni) {
                    const uint32_t* fh = &kh[ni >> 1][(ni & 1) * 2];
                    mma16816(s[ni], qfh[ks], fh);
                    mma16816(s[ni], qfl[ks], fh);
                }
            }

            const bool needm = (k0 + FA_BC - 1 > qr);
#pragma unroll
            for (int ni = 0; ni < 8; ++ni) {
                s[ni][0] *= 0.125f; s[ni][1] *= 0.125f;
                s[ni][2] *= 0.125f; s[ni][3] *= 0.125f;
                if (needm) {
                    int kp = k0 + ni * 8 + 2 * (lane & 3);
                    if (kp     > qp0) s[ni][0] = NEG_BIG;
                    if (kp + 1 > qp0) s[ni][1] = NEG_BIG;
                    if (kp     > qp1) s[ni][2] = NEG_BIG;
                    if (kp + 1 > qp1) s[ni][3] = NEG_BIG;
                }
            }

            float mx0 = NEG_BIG, mx1 = NEG_BIG;
#pragma unroll
            for (int ni = 0; ni < 8; ++ni) {
                mx0 = fmaxf(mx0, fmaxf(s[ni][0], s[ni][1]));
                mx1 = fmaxf(mx1, fmaxf(s[ni][2], s[ni][3]));
            }
            mx0 = fmaxf(mx0, __shfl_xor_sync(0xffffffffu, mx0, 1));
            mx0 = fmaxf(mx0, __shfl_xor_sync(0xffffffffu, mx0, 2));
            mx1 = fmaxf(mx1, __shfl_xor_sync(0xffffffffu, mx1, 1));
            mx1 = fmaxf(mx1, __shfl_xor_sync(0xffffffffu, mx1, 2));
            const float m0n = fmaxf(m0, mx0);
            const float m1n = fmaxf(m1, mx1);
            const float c0 = fexp(m0 - m0n);
            const float c1 = fexp(m1 - m1n);
            l0 *= c0; l1 *= c1;
#pragma unroll
            for (int ni = 0; ni < 8; ++ni) {
                o[ni][0] *= c0; o[ni][1] *= c0;
                o[ni][2] *= c1; o[ni][3] *= c1;
            }
            m0 = m0n; m1 = m1n;

#pragma unroll
            for (int ni = 0; ni < 8; ++ni) {
                s[ni][0] = fexp(s[ni][0] - m0);
                s[ni][1] = fexp(s[ni][1] - m0);
                s[ni][2] = fexp(s[ni][2] - m1);
                s[ni][3] = fexp(s[ni][3] - m1);
                l0 += s[ni][0] + s[ni][1];
                l1 += s[ni][2] + s[ni][3];
            }

#pragma unroll
            for (int ks = 0; ks < 4; ++ks) {
                uint32_t pah[4], pal[4];
                split2h(s[2*ks][0],   s[2*ks][1],   pah[0], pal[0]);
                split2h(s[2*ks][2],   s[2*ks][3],   pah[1], pal[1]);
                split2h(s[2*ks+1][0], s[2*ks+1][1], pah[2], pal[2]);
                split2h(s[2*ks+1][2], s[2*ks+1][3], pah[3], pal[3]);

                uint32_t vh[4][4];
#pragma unroll
                for (int nd = 0; nd < 4; ++nd) {
                    uint32_t off = (uint32_t)(ks * 16 + (lane & 15)) * FA_LDB
                                 + nd * 32 + (lane >> 4) * 16;
                    ldsm4t(vh[nd], tb + 1 * FA_TILE + off);
                }
#pragma unroll
                for (int ni = 0; ni < 8; ++ni) {
                    const uint32_t* fh = &vh[ni >> 1][(ni & 1) * 2];
                    mma16816(o[ni], pah, fh);
                    mma16816(o[ni], pal, fh);
                }
            }
        }
        if (++buf >= FA_NSTG) buf -= FA_NSTG;
    }

    // ---- epilogue: l reduction + fp16 hi/lo split store ----
    float L0 = l0 + __shfl_xor_sync(0xffffffffu, l0, 1);
    L0 += __shfl_xor_sync(0xffffffffu, L0, 2);
    float L1 = l1 + __shfl_xor_sync(0xffffffffu, l1, 1);
    L1 += __shfl_xor_sync(0xffffffffu, L1, 2);
    const float i0 = 1.0f / L0;
    const float i1 = 1.0f / L1;

    const size_t r0o = (size_t)(bT + qp0) * C_DIM + hoff + 2 * (lane & 3);
    const size_t r1o = (size_t)(bT + qp1) * C_DIM + hoff + 2 * (lane & 3);
#pragma unroll
    for (int ni = 0; ni < 8; ++ni) {
        uint32_t hh, ll;
        split2h(o[ni][0] * i0, o[ni][1] * i0, hh, ll);
        *(uint32_t*)(ath + r0o + ni * 8) = hh;
        *(uint32_t*)(atl + r0o + ni * 8) = ll;
        split2h(o[ni][2] * i1, o[ni][3] * i1, hh, ll);
        *(uint32_t*)(ath + r1o + ni * 8) = hh;
        *(uint32_t*)(atl + r1o + ni * 8) = ll;
    }
}

// ---------------------------------------------------------------------------
// Launch
// ---------------------------------------------------------------------------
extern "C" void kernel_launch(void* const* d_in, const int* in_sizes, int n_in,
                              void* d_out, int out_size)
{
    const float* x      = (const float*)d_in[0];
    const float* w_attn = (const float*)d_in[1];
    const float* b_attn = (const float*)d_in[2];
    const float* w_proj = (const float*)d_in[3];
    const float* b_proj = (const float*)d_in[4];
    float* out = (float*)d_out;

    void *p_qh, *p_ql, *p_xh, *p_xl, *p_wt, *p_wpt, *p_ath, *p_atl;
    cudaGetSymbolAddress(&p_qh,  g_qkvh);
    cudaGetSymbolAddress(&p_ql,  g_qkvl);
    cudaGetSymbolAddress(&p_xh,  g_xh);
    cudaGetSymbolAddress(&p_xl,  g_xl);
    cudaGetSymbolAddress(&p_wt,  g_wt);
    cudaGetSymbolAddress(&p_wpt, g_wpt);
    cudaGetSymbolAddress(&p_ath, g_ath);
    cudaGetSymbolAddress(&p_atl, g_atl);

    cudaFuncSetAttribute(gemm_mma<true>,
                         cudaFuncAttributeMaxDynamicSharedMemorySize, GEMM_SMEM);
    cudaFuncSetAttribute(gemm_mma<false>,
                         cudaFuncAttributeMaxDynamicSharedMemorySize, GEMM_SMEM);
    cudaFuncSetAttribute(flash_mma,
                         cudaFuncAttributeMaxDynamicSharedMemorySize, FA_SMEM);

    // 1) split x -> fp16 hi/lo
    {
        int n = M_ROWS * C_DIM;
        k_split<<<n / 4 / 256, 256>>>(x, (__half*)p_xh, (__half*)p_xl, n);
    }
    // 2) transpose weights -> fp16 single
    {
        dim3 g(N_QKV / 32, C_DIM / 32);
        k_transpose_half<<<g, dim3(32, 8)>>>(w_attn, (__half*)p_wt, C_DIM, N_QKV);
    }
    {
        dim3 g(C_DIM / 32, C_DIM / 32);
        k_transpose_half<<<g, dim3(32, 8)>>>(w_proj, (__half*)p_wpt, C_DIM, C_DIM);
    }
    // 3) qkv = x @ w_attn + b_attn  (HMMA, direct fp16 hi/lo output)
    {
        dim3 grid(N_QKV / 256, M_ROWS / 128);
        gemm_mma<true><<<grid, 256, GEMM_SMEM>>>(
            (const __half*)p_xh, (const __half*)p_xl, (const __half*)p_wt,
            b_attn, nullptr,
            (__half*)p_qh, (__half*)p_ql, N_QKV, C_DIM);
    }
    // 4) causal MHA (HMMA flash, direct fp16 hi/lo output)
    {
        dim3 grid(B_DIM * H_DIM, T_DIM / FA_BQ);
        flash_mma<<<grid, 256, FA_SMEM>>>((const __half*)p_qh,
                                          (const __half*)p_ql,
                                          (__half*)p_ath,
                                          (__half*)p_atl);
    }
    // 5) out = att @ w_proj + b_proj (HMMA, fp32 output)
    {
        dim3 grid(C_DIM / 256, M_ROWS / 128);
        gemm_mma<false><<<grid, 256, GEMM_SMEM>>>(
            (const __half*)p_ath, (const __half*)p_atl, (const __half*)p_wpt,
            b_proj, out, nullptr, nullptr, C_DIM, C_DIM);
    }
}

// round 10
// speedup vs baseline: 1.1393x; 1.1393x over previous
#include <cuda_runtime.h>
#include <cuda_fp16.h>
#include <math_constants.h>
#include <cstdint>

// ---------------------------------------------------------------------------
// Problem constants
// ---------------------------------------------------------------------------
#define B_DIM 4
#define T_DIM 2048
#define C_DIM 1024
#define H_DIM 16
#define D_DIM 64
#define M_ROWS (B_DIM * T_DIM)       // 8192
#define N_QKV  (3 * C_DIM)           // 3072

// ---------------------------------------------------------------------------
// Device scratch (allocation-free rule)
// ---------------------------------------------------------------------------
__device__ __half g_qkvh[(size_t)M_ROWS * N_QKV];   // qkv fp16 hi (Q pre-scaled)
__device__ __half g_qkvl[(size_t)M_ROWS * N_QKV];   // qkv fp16 lo (Q cols only)
__device__ __half g_xh[(size_t)M_ROWS * C_DIM];
__device__ __half g_xl[(size_t)M_ROWS * C_DIM];
__device__ __half g_wt[(size_t)N_QKV * C_DIM];      // w_attn^T fp16 [3072][1024]
__device__ __half g_wpt[(size_t)C_DIM * C_DIM];     // w_proj^T fp16 [1024][1024]
__device__ __half g_ath[(size_t)M_ROWS * C_DIM];
__device__ __half g_atl[(size_t)M_ROWS * C_DIM];

// ---------------------------------------------------------------------------
// Helpers
// ---------------------------------------------------------------------------
__device__ __forceinline__ uint32_t smem_u32(const void* p) {
    uint32_t a;
    asm("{ .reg .u64 t; cvta.to.shared.u64 t, %1; cvt.u32.u64 %0, t; }"
        : "=r"(a) : "l"(p));
    return a;
}

__device__ __forceinline__ void cp16(uint32_t dst, const void* src) {
    asm volatile("cp.async.cg.shared.global [%0], [%1], 16;"
                 :: "r"(dst), "l"(src));
}
#define CP_COMMIT() asm volatile("cp.async.commit_group;" ::: "memory")
#define CP_WAIT(n)  asm volatile("cp.async.wait_group %0;" :: "n"(n) : "memory")

__device__ __forceinline__ void ldsm4(uint32_t* r, uint32_t addr) {
    asm volatile("ldmatrix.sync.aligned.m8n8.x4.shared.b16 {%0,%1,%2,%3}, [%4];"
                 : "=r"(r[0]), "=r"(r[1]), "=r"(r[2]), "=r"(r[3]) : "r"(addr));
}

__device__ __forceinline__ void ldsm4t(uint32_t* r, uint32_t addr) {
    asm volatile("ldmatrix.sync.aligned.m8n8.x4.trans.shared.b16 {%0,%1,%2,%3}, [%4];"
                 : "=r"(r[0]), "=r"(r[1]), "=r"(r[2]), "=r"(r[3]) : "r"(addr));
}

__device__ __forceinline__ void mma16816(float* c, const uint32_t* a,
                                         const uint32_t* b) {
    asm volatile(
        "mma.sync.aligned.m16n8k16.row.col.f32.f16.f16.f32 "
        "{%0,%1,%2,%3}, {%4,%5,%6,%7}, {%8,%9}, {%0,%1,%2,%3};"
        : "+f"(c[0]), "+f"(c[1]), "+f"(c[2]), "+f"(c[3])
        : "r"(a[0]), "r"(a[1]), "r"(a[2]), "r"(a[3]), "r"(b[0]), "r"(b[1]));
}

// Split a pair of floats into packed fp16 hi / lo uint32 fragments
__device__ __forceinline__ void split2h(float x, float y, uint32_t& h, uint32_t& l) {
    __half hx = __float2half(x);
    __half hy = __float2half(y);
    __half lx = __float2half(x - __half2float(hx));
    __half ly = __float2half(y - __half2float(hy));
    __half2 hp(hx, hy), lp(lx, ly);
    h = *reinterpret_cast<uint32_t*>(&hp);
    l = *reinterpret_cast<uint32_t*>(&lp);
}

// ---------------------------------------------------------------------------
// Prep kernels
// ---------------------------------------------------------------------------
__global__ void k_split(const float* __restrict__ in,
                        __half* __restrict__ hi,
                        __half* __restrict__ lo, int n)
{
    int i = (blockIdx.x * blockDim.x + threadIdx.x) * 4;
    if (i >= n) return;
    float4 v = *(const float4*)(in + i);
    float f[4] = {v.x, v.y, v.z, v.w};
    __half h[4], l[4];
#pragma unroll
    for (int j = 0; j < 4; ++j) {
        h[j] = __float2half(f[j]);
        l[j] = __float2half(f[j] - __half2float(h[j]));
    }
    *(__half2*)(hi + i)     = __half2(h[0], h[1]);
    *(__half2*)(hi + i + 2) = __half2(h[2], h[3]);
    *(__half2*)(lo + i)     = __half2(l[0], l[1]);
    *(__half2*)(lo + i + 2) = __half2(l[2], l[3]);
}

// W[K][N] row-major -> T[N][K] fp16 (single)
__global__ void k_transpose_half(const float* __restrict__ W,
                                 __half* __restrict__ T, int K, int N)
{
    __shared__ float tile[32][33];
    const int k0 = blockIdx.y * 32;
    const int n0 = blockIdx.x * 32;
    const int tx = threadIdx.x;
    const int ty = threadIdx.y;
#pragma unroll
    for (int r = 0; r < 4; ++r)
        tile[ty + r * 8][tx] = W[(size_t)(k0 + ty + r * 8) * N + n0 + tx];
    __syncthreads();
#pragma unroll
    for (int r = 0; r < 4; ++r) {
        float v = tile[tx][ty + r * 8];
        T[(size_t)(n0 + ty + r * 8) * K + k0 + tx] = __float2half(v);
    }
}

// ---------------------------------------------------------------------------
// HMMA GEMM (R8 config): C = A @ Bt^T + bias.
// A = fp16 hi/lo 2-product, B = fp16 single.
// 128x128 CTA tile, BK=32, 8 warps (32x64), 3-stage ring, one barrier/chunk,
// 2 CTAs/SM. SPLIT_OUT: write fp16 hi/lo; Q columns pre-scaled by 0.125.
// ---------------------------------------------------------------------------
#define BKC  32
#define LDSB 80                       // smem row stride bytes
#define TILE (128 * LDSB)             // 10240 per operand tile
#define STG  (3 * TILE)               // Ah, Al, B = 30720 per stage
#define NSTG 3
#define GEMM_SMEM (NSTG * STG)        // 92160 -> 2 CTAs/SM

template<bool SPLIT_OUT>
__global__ void __launch_bounds__(256, 2)
gemm_mma(const __half* __restrict__ Ah, const __half* __restrict__ Al,
         const __half* __restrict__ Bf,
         const float* __restrict__ bias, float* __restrict__ C,
         __half* __restrict__ Ch, __half* __restrict__ Cl,
         int N, int K)
{
    extern __shared__ char sm[];
    const uint32_t sbase = smem_u32(sm);

    const int tid  = threadIdx.x;
    const int lane = tid & 31;
    const int wid  = tid >> 5;
    const int m0 = blockIdx.y * 128;
    const int n0 = blockIdx.x * 128;
    const int wm = (wid & 3) * 32;        // 4 warps along M
    const int wn = (wid >> 2) * 64;       // 2 warps along N

    float acc[2][8][4];
#pragma unroll
    for (int i = 0; i < 2; ++i)
#pragma unroll
        for (int j = 0; j < 8; ++j)
#pragma unroll
            for (int k = 0; k < 4; ++k) acc[i][j][k] = 0.0f;

    const int r0 = tid >> 2, c0 = tid & 3;
    const int r1 = r0 + 64;
    const __half* pAh0 = Ah + (size_t)(m0 + r0) * K + c0 * 8;
    const __half* pAh1 = Ah + (size_t)(m0 + r1) * K + c0 * 8;
    const __half* pAl0 = Al + (size_t)(m0 + r0) * K + c0 * 8;
    const __half* pAl1 = Al + (size_t)(m0 + r1) * K + c0 * 8;
    const __half* pB0  = Bf + (size_t)(n0 + r0) * K + c0 * 8;
    const __half* pB1  = Bf + (size_t)(n0 + r1) * K + c0 * 8;
    const uint32_t dA0 = (uint32_t)r0 * LDSB + (uint32_t)c0 * 16;
    const uint32_t dA1 = (uint32_t)r1 * LDSB + (uint32_t)c0 * 16;

    auto load_chunk = [&](int c, int buf) {
        const int koff = c * BKC;
        const uint32_t db = sbase + buf * STG;
        cp16(db + 0 * TILE + dA0, pAh0 + koff);
        cp16(db + 0 * TILE + dA1, pAh1 + koff);
        cp16(db + 1 * TILE + dA0, pAl0 + koff);
        cp16(db + 1 * TILE + dA1, pAl1 + koff);
        cp16(db + 2 * TILE + dA0, pB0 + koff);
        cp16(db + 2 * TILE + dA1, pB1 + koff);
        CP_COMMIT();
    };

    const int NC = K / BKC;
    load_chunk(0, 0);
    load_chunk(1, 1);

    int buf = 0;
    for (int c = 0; c < NC; ++c) {
        if (c + 1 < NC) { CP_WAIT(1); } else { CP_WAIT(0); }
        __syncthreads();
        if (c + 2 < NC) {
            int nb = buf + 2; if (nb >= NSTG) nb -= NSTG;
            load_chunk(c + 2, nb);
        }

        const uint32_t tb = sbase + buf * STG;
#pragma unroll
        for (int ks = 0; ks < 2; ++ks) {
            uint32_t ah[2][4], al[2][4];
#pragma unroll
            for (int mi = 0; mi < 2; ++mi) {
                uint32_t off = (uint32_t)(wm + mi * 16 + (lane & 15)) * LDSB
                             + ks * 32 + (lane >> 4) * 16;
                ldsm4(ah[mi], tb + 0 * TILE + off);
                ldsm4(al[mi], tb + 1 * TILE + off);
            }
#pragma unroll
            for (int np = 0; np < 4; ++np) {
                uint32_t bf[4];
                uint32_t off = (uint32_t)(wn + np * 16 + (lane & 7)
                             + ((lane >> 4) & 1) * 8) * LDSB
                             + ks * 32 + ((lane >> 3) & 1) * 16;
                ldsm4(bf, tb + 2 * TILE + off);
#pragma unroll
                for (int mi = 0; mi < 2; ++mi)
#pragma unroll
                    for (int nj = 0; nj < 2; ++nj) {
                        float* a = acc[mi][2 * np + nj];
                        mma16816(a, ah[mi], &bf[nj * 2]);
                        mma16816(a, al[mi], &bf[nj * 2]);
                    }
            }
        }
        if (++buf >= NSTG) buf -= NSTG;
    }

#pragma unroll
    for (int mi = 0; mi < 2; ++mi) {
        const int row = m0 + wm + mi * 16 + (lane >> 2);
#pragma unroll
        for (int ni = 0; ni < 8; ++ni) {
            const int col = n0 + wn + ni * 8 + (lane & 3) * 2;
            const float b0v = bias[col];
            const float b1v = bias[col + 1];
            float v0x = acc[mi][ni][0] + b0v;
            float v0y = acc[mi][ni][1] + b1v;
            float v1x = acc[mi][ni][2] + b0v;
            float v1y = acc[mi][ni][3] + b1v;
            if (SPLIT_OUT) {
                const bool isq = (col < C_DIM);
                if (isq) {   // pre-scale Q by 1/sqrt(D); exact (power of 2)
                    v0x *= 0.125f; v0y *= 0.125f;
                    v1x *= 0.125f; v1y *= 0.125f;
                }
                uint32_t h0, l0, h1, l1;
                split2h(v0x, v0y, h0, l0);
                split2h(v1x, v1y, h1, l1);
                const size_t o0 = (size_t)row * N + col;
                const size_t o1 = (size_t)(row + 8) * N + col;
                *(uint32_t*)(Ch + o0) = h0;
                *(uint32_t*)(Ch + o1) = h1;
                if (isq) {               // lo only ever read for Q columns
                    *(uint32_t*)(Cl + o0) = l0;
                    *(uint32_t*)(Cl + o1) = l1;
                }
            } else {
                float2 v0, v1;
                v0.x = v0x; v0.y = v0y;
                v1.x = v1x; v1.y = v1y;
                *(float2*)(C + (size_t)row * N + col)       = v0;
                *(float2*)(C + (size_t)(row + 8) * N + col) = v1;
            }
        }
    }
}

// ---------------------------------------------------------------------------
// HMMA causal flash attention (R8 structure). CTA: 128 q-rows x one (b,h).
// Q pre-scaled; exps on MUFU (__expf) to free the FMA pipe.
// 3-stage K/V ring, one barrier per tile, 2 CTAs/SM.
// ---------------------------------------------------------------------------
#define FA_BQ   128
#define FA_BC   64
#define FA_LDB  144
#define FA_QH   0
#define FA_QL   (FA_BQ * FA_LDB)
#define FA_BUF  (2 * FA_BQ * FA_LDB)     // 36864: Q hi+lo
#define FA_TILE (FA_BC * FA_LDB)         // 9216
#define FA_BUFSZ (2 * FA_TILE)           // 18432 (Kh, Vh)
#define FA_NSTG 3
#define FA_SMEM (FA_BUF + FA_NSTG * FA_BUFSZ)  // 92160
#define NEG_BIG (-1e30f)

__global__ void __launch_bounds__(256, 2)
flash_mma(const __half* __restrict__ qh,
          const __half* __restrict__ ql,
          __half* __restrict__ ath,
          __half* __restrict__ atl)
{
    extern __shared__ char fsm[];
    const uint32_t sb = smem_u32(fsm);

    const int tid  = threadIdx.x;
    const int lane = tid & 31;
    const int wid  = tid >> 5;
    const int b = blockIdx.x >> 4;
    const int h = blockIdx.x & 15;
    const int yy = (int)gridDim.y - 1 - (int)blockIdx.y;   // heavy tiles first
    const int q0 = yy * FA_BQ;
    const int NT = 2 * (yy + 1);
    const int bT = b * T_DIM;
    const int hoff = h * D_DIM;

    auto load_tile = [&](int t, int bufi) {
        const int k0 = t * FA_BC;
        const int row = tid >> 2;
        const int ch2 = (tid & 3) * 2;
        const size_t rb = (size_t)(bT + k0 + row) * N_QKV + hoff;
        const uint32_t tb = sb + FA_BUF + bufi * FA_BUFSZ;
        const uint32_t d = tb + row * FA_LDB + ch2 * 16;
        const __half* skh = qh + rb + C_DIM;
        const __half* svh = qh + rb + 2 * C_DIM;
        cp16(d + 0 * FA_TILE,      skh + ch2 * 8);
        cp16(d + 0 * FA_TILE + 16, skh + ch2 * 8 + 8);
        cp16(d + 1 * FA_TILE,      svh + ch2 * 8);
        cp16(d + 1 * FA_TILE + 16, svh + ch2 * 8 + 8);
        CP_COMMIT();
    };

    // ---- issue Q tile load, then prefetch K/V tiles 0 & 1 ----
#pragma unroll
    for (int i = 0; i < 8; ++i) {
        int idx = tid + i * 256;
        int arr = idx >> 10;
        int wi  = idx & 1023;
        int row = wi >> 3;
        int ch  = wi & 7;
        const __half* src = (arr ? ql : qh)
            + (size_t)(bT + q0 + row) * N_QKV + hoff + ch * 8;
        cp16(sb + arr * (FA_BQ * FA_LDB) + row * FA_LDB + ch * 16, src);
    }
    CP_COMMIT();
    load_tile(0, 0);
    load_tile(1, 1);          // NT >= 2 always

    CP_WAIT(2);               // Q done; K/V tiles may still be in flight
    __syncthreads();

    uint32_t qfh[4][4], qfl[4][4];
#pragma unroll
    for (int ks = 0; ks < 4; ++ks) {
        uint32_t off = (uint32_t)(wid * 16 + (lane & 15)) * FA_LDB
                     + ks * 32 + (lane >> 4) * 16;
        ldsm4(qfh[ks], sb + FA_QH + off);
        ldsm4(qfl[ks], sb + FA_QL + off);
    }

    float o[8][4];
#pragma unroll
    for (int i = 0; i < 8; ++i)
#pragma unroll
        for (int j = 0; j < 4; ++j) o[i][j] = 0.0f;
    float m0 = NEG_BIG, m1 = NEG_BIG, l0 = 0.0f, l1 = 0.0f;
    const int qr  = q0 + wid * 16;
    const int qp0 = qr + (lane >> 2);
    const int qp1 = qp0 + 8;

    int buf = 0;
    for (int t = 0; t < NT; ++t) {
        if (t + 1 < NT) { CP_WAIT(1); } else { CP_WAIT(0); }
        __syncthreads();
        if (t + 2 < NT) {
            int nb = buf + 2; if (nb >= FA_NSTG) nb -= FA_NSTG;
            load_tile(t + 2, nb);
        }

        const int k0 = t * FA_BC;
        if (k0 <= qr + 15) {
            const uint32_t tb = sb + FA_BUF + buf * FA_BUFSZ;

            float s[8][4];
#pragma unroll
            for (int i = 0; i < 8; ++i)
#pragma unroll
                for (int j = 0; j < 4; ++j) s[i][j] = 0.0f;

#pragma unroll
            for (int ks = 0; ks < 4; ++ks) {
                uint32_t kh[4][4];
#pragma unroll
                for (int np = 0; np < 4; ++np) {
                    uint32_t off = (uint32_t)(np * 16 + (lane & 7)
                                 + ((lane >> 4) & 1) * 8) * FA_LDB
                                 + ks * 32 + ((lane >> 3) & 1) * 16;
                    ldsm4(kh[np], tb + 0 * FA_TILE + off);
                }
#pragma unroll
                for (int ni = 0; ni < 8; ++ni) {
                    const uint32_t* fh = &kh[ni >> 1][(ni & 1) * 2];
                    mma16816(s[ni], qfh[ks], fh);
                    mma16816(s[ni], qfl[ks], fh);
                }
            }

            // causal mask (scores already scaled: Q pre-scaled by 0.125)
            if (k0 + FA_BC - 1 > qr) {
#pragma unroll
                for (int ni = 0; ni < 8; ++ni) {
                    int kp = k0 + ni * 8 + 2 * (lane & 3);
                    if (kp     > qp0) s[ni][0] = NEG_BIG;
                    if (kp + 1 > qp0) s[ni][1] = NEG_BIG;
                    if (kp     > qp1) s[ni][2] = NEG_BIG;
                    if (kp + 1 > qp1) s[ni][3] = NEG_BIG;
                }
            }

            float mx0 = NEG_BIG, mx1 = NEG_BIG;
#pragma unroll
            for (int ni = 0; ni < 8; ++ni) {
                mx0 = fmaxf(mx0, fmaxf(s[ni][0], s[ni][1]));
                mx1 = fmaxf(mx1, fmaxf(s[ni][2], s[ni][3]));
            }
            mx0 = fmaxf(mx0, __shfl_xor_sync(0xffffffffu, mx0, 1));
            mx0 = fmaxf(mx0, __shfl_xor_sync(0xffffffffu, mx0, 2));
            mx1 = fmaxf(mx1, __shfl_xor_sync(0xffffffffu, mx1, 1));
            mx1 = fmaxf(mx1, __shfl_xor_sync(0xffffffffu, mx1, 2));
            const float m0n = fmaxf(m0, mx0);
            const float m1n = fmaxf(m1, mx1);
            const float c0 = __expf(m0 - m0n);
            const float c1 = __expf(m1 - m1n);
            l0 *= c0; l1 *= c1;
#pragma unroll
            for (int ni = 0; ni < 8; ++ni) {
                o[ni][0] *= c0; o[ni][1] *= c0;
                o[ni][2] *= c1; o[ni][3] *= c1;
            }
            m0 = m0n; m1 = m1n;

#pragma unroll
            for (int ni = 0; ni < 8; ++ni) {
                s[ni][0] = __expf(s[ni][0] - m0);
                s[ni][1] = __expf(s[ni][1] - m0);
                s[ni][2] = __expf(s[ni][2] - m1);
                s[ni][3] = __expf(s[ni][3] - m1);
                l0 += s[ni][0] + s[ni][1];
                l1 += s[ni][2] + s[ni][3];
            }

#pragma unroll
            for (int ks = 0; ks < 4; ++ks) {
                uint32_t pah[4], pal[4];
                split2h(s[2*ks][0],   s[2*ks][1],   pah[0], pal[0]);
                split2h(s[2*ks][2],   s[2*ks][3],   pah[1], pal[1]);
                split2h(s[2*ks+1][0], s[2*ks+1][1], pah[2], pal[2]);
                split2h(s[2*ks+1][2], s[2*ks+1][3], pah[3], pal[3]);

                uint32_t vh[4][4];
#pragma unroll
                for (int nd = 0; nd < 4; ++nd) {
                    uint32_t off = (uint32_t)(ks * 16 + (lane & 15)) * FA_LDB
                                 + nd * 32 + (lane >> 4) * 16;
                    ldsm4t(vh[nd], tb + 1 * FA_TILE + off);
                }
#pragma unroll
                for (int ni = 0; ni < 8; ++ni) {
                    const uint32_t* fh = &vh[ni >> 1][(ni & 1) * 2];
                    mma16816(o[ni], pah, fh);
                    mma16816(o[ni], pal, fh);
                }
            }
        }
        if (++buf >= FA_NSTG) buf -= FA_NSTG;
    }

    // ---- epilogue: l reduction + fp16 hi/lo split store ----
    float L0 = l0 + __shfl_xor_sync(0xffffffffu, l0, 1);
    L0 += __shfl_xor_sync(0xffffffffu, L0, 2);
    float L1 = l1 + __shfl_xor_sync(0xffffffffu, l1, 1);
    L1 += __shfl_xor_sync(0xffffffffu, L1, 2);
    const float i0 = 1.0f / L0;
    const float i1 = 1.0f / L1;

    const size_t r0o = (size_t)(bT + qp0) * C_DIM + hoff + 2 * (lane & 3);
    const size_t r1o = (size_t)(bT + qp1) * C_DIM + hoff + 2 * (lane & 3);
#pragma unroll
    for (int ni = 0; ni < 8; ++ni) {
        uint32_t hh, ll;
        split2h(o[ni][0] * i0, o[ni][1] * i0, hh, ll);
        *(uint32_t*)(ath + r0o + ni * 8) = hh;
        *(uint32_t*)(atl + r0o + ni * 8) = ll;
        split2h(o[ni][2] * i1, o[ni][3] * i1, hh, ll);
        *(uint32_t*)(ath + r1o + ni * 8) = hh;
        *(uint32_t*)(atl + r1o + ni * 8) = ll;
    }
}

// ---------------------------------------------------------------------------
// Launch
// ---------------------------------------------------------------------------
extern "C" void kernel_launch(void* const* d_in, const int* in_sizes, int n_in,
                              void* d_out, int out_size)
{
    const float* x      = (const float*)d_in[0];
    const float* w_attn = (const float*)d_in[1];
    const float* b_attn = (const float*)d_in[2];
    const float* w_proj = (const float*)d_in[3];
    const float* b_proj = (const float*)d_in[4];
    float* out = (float*)d_out;

    void *p_qh, *p_ql, *p_xh, *p_xl, *p_wt, *p_wpt, *p_ath, *p_atl;
    cudaGetSymbolAddress(&p_qh,  g_qkvh);
    cudaGetSymbolAddress(&p_ql,  g_qkvl);
    cudaGetSymbolAddress(&p_xh,  g_xh);
    cudaGetSymbolAddress(&p_xl,  g_xl);
    cudaGetSymbolAddress(&p_wt,  g_wt);
    cudaGetSymbolAddress(&p_wpt, g_wpt);
    cudaGetSymbolAddress(&p_ath, g_ath);
    cudaGetSymbolAddress(&p_atl, g_atl);

    cudaFuncSetAttribute(gemm_mma<true>,
                         cudaFuncAttributeMaxDynamicSharedMemorySize, GEMM_SMEM);
    cudaFuncSetAttribute(gemm_mma<false>,
                         cudaFuncAttributeMaxDynamicSharedMemorySize, GEMM_SMEM);
    cudaFuncSetAttribute(flash_mma,
                         cudaFuncAttributeMaxDynamicSharedMemorySize, FA_SMEM);

    // 1) split x -> fp16 hi/lo
    {
        int n = M_ROWS * C_DIM;
        k_split<<<n / 4 / 256, 256>>>(x, (__half*)p_xh, (__half*)p_xl, n);
    }
    // 2) transpose weights -> fp16 single
    {
        dim3 g(N_QKV / 32, C_DIM / 32);
        k_transpose_half<<<g, dim3(32, 8)>>>(w_attn, (__half*)p_wt, C_DIM, N_QKV);
    }
    {
        dim3 g(C_DIM / 32, C_DIM / 32);
        k_transpose_half<<<g, dim3(32, 8)>>>(w_proj, (__half*)p_wpt, C_DIM, C_DIM);
    }
    // 3) qkv = x @ w_attn + b_attn  (HMMA, fp16 hi/lo output, Q pre-scaled)
    {
        dim3 grid(N_QKV / 128, M_ROWS / 128);
        gemm_mma<true><<<grid, 256, GEMM_SMEM>>>(
            (const __half*)p_xh, (const __half*)p_xl, (const __half*)p_wt,
            b_attn, nullptr,
            (__half*)p_qh, (__half*)p_ql, N_QKV, C_DIM);
    }
    // 4) causal MHA (HMMA flash, direct fp16 hi/lo output)
    {
        dim3 grid(B_DIM * H_DIM, T_DIM / FA_BQ);
        flash_mma<<<grid, 256, FA_SMEM>>>((const __half*)p_qh,
                                          (const __half*)p_ql,
                                          (__half*)p_ath,
                                          (__half*)p_atl);
    }
    // 5) out = att @ w_proj + b_proj (HMMA, fp32 output)
    {
        dim3 grid(C_DIM / 128, M_ROWS / 128);
        gemm_mma<false><<<grid, 256, GEMM_SMEM>>>(
            (const __half*)p_ath, (const __half*)p_atl, (const __half*)p_wpt,
            b_proj, out, nullptr, nullptr, C_DIM, C_DIM);
    }
}

// round 11
// speedup vs baseline: 1.1950x; 1.0488x over previous
#include <cuda_runtime.h>
#include <cuda_fp16.h>
#include <math_constants.h>
#include <cstdint>

// ---------------------------------------------------------------------------
// Problem constants
// ---------------------------------------------------------------------------
#define B_DIM 4
#define T_DIM 2048
#define C_DIM 1024
#define H_DIM 16
#define D_DIM 64
#define M_ROWS (B_DIM * T_DIM)       // 8192
#define N_QKV  (3 * C_DIM)           // 3072

// ---------------------------------------------------------------------------
// Device scratch (allocation-free rule)
// ---------------------------------------------------------------------------
__device__ __half g_qkvh[(size_t)M_ROWS * N_QKV];   // qkv fp16 hi (Q pre-scaled)
__device__ __half g_qkvl[(size_t)M_ROWS * N_QKV];   // qkv fp16 lo (Q cols only)
__device__ __half g_xh[(size_t)M_ROWS * C_DIM];
__device__ __half g_xl[(size_t)M_ROWS * C_DIM];
__device__ __half g_wt[(size_t)N_QKV * C_DIM];      // w_attn^T fp16 [3072][1024]
__device__ __half g_wpt[(size_t)C_DIM * C_DIM];     // w_proj^T fp16 [1024][1024]
__device__ __half g_ath[(size_t)M_ROWS * C_DIM];
__device__ __half g_atl[(size_t)M_ROWS * C_DIM];

// ---------------------------------------------------------------------------
// Helpers
// ---------------------------------------------------------------------------
__device__ __forceinline__ uint32_t smem_u32(const void* p) {
    uint32_t a;
    asm("{ .reg .u64 t; cvta.to.shared.u64 t, %1; cvt.u32.u64 %0, t; }"
        : "=r"(a) : "l"(p));
    return a;
}

__device__ __forceinline__ void cp16(uint32_t dst, const void* src) {
    asm volatile("cp.async.cg.shared.global [%0], [%1], 16;"
                 :: "r"(dst), "l"(src));
}
#define CP_COMMIT() asm volatile("cp.async.commit_group;" ::: "memory")
#define CP_WAIT(n)  asm volatile("cp.async.wait_group %0;" :: "n"(n) : "memory")

__device__ __forceinline__ void ldsm4(uint32_t* r, uint32_t addr) {
    asm volatile("ldmatrix.sync.aligned.m8n8.x4.shared.b16 {%0,%1,%2,%3}, [%4];"
                 : "=r"(r[0]), "=r"(r[1]), "=r"(r[2]), "=r"(r[3]) : "r"(addr));
}

__device__ __forceinline__ void ldsm4t(uint32_t* r, uint32_t addr) {
    asm volatile("ldmatrix.sync.aligned.m8n8.x4.trans.shared.b16 {%0,%1,%2,%3}, [%4];"
                 : "=r"(r[0]), "=r"(r[1]), "=r"(r[2]), "=r"(r[3]) : "r"(addr));
}

__device__ __forceinline__ void mma16816(float* c, const uint32_t* a,
                                         const uint32_t* b) {
    asm volatile(
        "mma.sync.aligned.m16n8k16.row.col.f32.f16.f16.f32 "
        "{%0,%1,%2,%3}, {%4,%5,%6,%7}, {%8,%9}, {%0,%1,%2,%3};"
        : "+f"(c[0]), "+f"(c[1]), "+f"(c[2]), "+f"(c[3])
        : "r"(a[0]), "r"(a[1]), "r"(a[2]), "r"(a[3]), "r"(b[0]), "r"(b[1]));
}

// Split a pair of floats into packed fp16 hi / lo uint32 fragments
__device__ __forceinline__ void split2h(float x, float y, uint32_t& h, uint32_t& l) {
    __half hx = __float2half(x);
    __half hy = __float2half(y);
    __half lx = __float2half(x - __half2float(hx));
    __half ly = __float2half(y - __half2float(hy));
    __half2 hp(hx, hy), lp(lx, ly);
    h = *reinterpret_cast<uint32_t*>(&hp);
    l = *reinterpret_cast<uint32_t*>(&lp);
}

// ---------------------------------------------------------------------------
// Prep kernels
// ---------------------------------------------------------------------------
__global__ void k_split(const float* __restrict__ in,
                        __half* __restrict__ hi,
                        __half* __restrict__ lo, int n)
{
    int i = (blockIdx.x * blockDim.x + threadIdx.x) * 4;
    if (i >= n) return;
    float4 v = *(const float4*)(in + i);
    float f[4] = {v.x, v.y, v.z, v.w};
    __half h[4], l[4];
#pragma unroll
    for (int j = 0; j < 4; ++j) {
        h[j] = __float2half(f[j]);
        l[j] = __float2half(f[j] - __half2float(h[j]));
    }
    *(__half2*)(hi + i)     = __half2(h[0], h[1]);
    *(__half2*)(hi + i + 2) = __half2(h[2], h[3]);
    *(__half2*)(lo + i)     = __half2(l[0], l[1]);
    *(__half2*)(lo + i + 2) = __half2(l[2], l[3]);
}

// W[K][N] row-major -> T[N][K] fp16 (single)
__global__ void k_transpose_half(const float* __restrict__ W,
                                 __half* __restrict__ T, int K, int N)
{
    __shared__ float tile[32][33];
    const int k0 = blockIdx.y * 32;
    const int n0 = blockIdx.x * 32;
    const int tx = threadIdx.x;
    const int ty = threadIdx.y;
#pragma unroll
    for (int r = 0; r < 4; ++r)
        tile[ty + r * 8][tx] = W[(size_t)(k0 + ty + r * 8) * N + n0 + tx];
    __syncthreads();
#pragma unroll
    for (int r = 0; r < 4; ++r) {
        float v = tile[tx][ty + r * 8];
        T[(size_t)(n0 + ty + r * 8) * K + k0 + tx] = __float2half(v);
    }
}

// ---------------------------------------------------------------------------
// HMMA GEMM: C = A @ Bt^T + bias.
// A = fp16 hi/lo 2-product for Q/proj columns; 1-product (hi only) for K/V
// columns (their outputs are stored fp16-hi anyway, so lo adds no accuracy).
// 128x128 CTA tile, BK=32, 8 warps (32x64), 3-stage ring, one barrier/chunk,
// 2 CTAs/SM. SPLIT_OUT: write fp16 hi/lo; Q columns pre-scaled by 0.125.
// ---------------------------------------------------------------------------
#define BKC  32
#define LDSB 80                       // smem row stride bytes
#define TILE (128 * LDSB)             // 10240 per operand tile
#define STG  (3 * TILE)               // Ah, Al, B = 30720 per stage
#define NSTG 3
#define GEMM_SMEM (NSTG * STG)        // 92160 -> 2 CTAs/SM

template<bool SPLIT_OUT>
__global__ void __launch_bounds__(256, 2)
gemm_mma(const __half* __restrict__ Ah, const __half* __restrict__ Al,
         const __half* __restrict__ Bf,
         const float* __restrict__ bias, float* __restrict__ C,
         __half* __restrict__ Ch, __half* __restrict__ Cl,
         int N, int K)
{
    extern __shared__ char sm[];
    const uint32_t sbase = smem_u32(sm);

    const int tid  = threadIdx.x;
    const int lane = tid & 31;
    const int wid  = tid >> 5;
    const int m0 = blockIdx.y * 128;
    const int n0 = blockIdx.x * 128;
    const int wm = (wid & 3) * 32;        // 4 warps along M
    const int wn = (wid >> 2) * 64;       // 2 warps along N

    // CTA-uniform: K/V output columns are fp16-hi only -> skip the lo product
    const bool use_lo = (!SPLIT_OUT) || (n0 < C_DIM);

    float acc[2][8][4];
#pragma unroll
    for (int i = 0; i < 2; ++i)
#pragma unroll
        for (int j = 0; j < 8; ++j)
#pragma unroll
            for (int k = 0; k < 4; ++k) acc[i][j][k] = 0.0f;

    const int r0 = tid >> 2, c0 = tid & 3;
    const int r1 = r0 + 64;
    const __half* pAh0 = Ah + (size_t)(m0 + r0) * K + c0 * 8;
    const __half* pAh1 = Ah + (size_t)(m0 + r1) * K + c0 * 8;
    const __half* pAl0 = Al + (size_t)(m0 + r0) * K + c0 * 8;
    const __half* pAl1 = Al + (size_t)(m0 + r1) * K + c0 * 8;
    const __half* pB0  = Bf + (size_t)(n0 + r0) * K + c0 * 8;
    const __half* pB1  = Bf + (size_t)(n0 + r1) * K + c0 * 8;
    const uint32_t dA0 = (uint32_t)r0 * LDSB + (uint32_t)c0 * 16;
    const uint32_t dA1 = (uint32_t)r1 * LDSB + (uint32_t)c0 * 16;

    auto load_chunk = [&](int c, int buf) {
        const int koff = c * BKC;
        const uint32_t db = sbase + buf * STG;
        cp16(db + 0 * TILE + dA0, pAh0 + koff);
        cp16(db + 0 * TILE + dA1, pAh1 + koff);
        if (use_lo) {
            cp16(db + 1 * TILE + dA0, pAl0 + koff);
            cp16(db + 1 * TILE + dA1, pAl1 + koff);
        }
        cp16(db + 2 * TILE + dA0, pB0 + koff);
        cp16(db + 2 * TILE + dA1, pB1 + koff);
        CP_COMMIT();
    };

    const int NC = K / BKC;
    load_chunk(0, 0);
    load_chunk(1, 1);

    int buf = 0;
    for (int c = 0; c < NC; ++c) {
        if (c + 1 < NC) { CP_WAIT(1); } else { CP_WAIT(0); }
        __syncthreads();
        if (c + 2 < NC) {
            int nb = buf + 2; if (nb >= NSTG) nb -= NSTG;
            load_chunk(c + 2, nb);
        }

        const uint32_t tb = sbase + buf * STG;
#pragma unroll
        for (int ks = 0; ks < 2; ++ks) {
            uint32_t ah[2][4], al[2][4];
#pragma unroll
            for (int mi = 0; mi < 2; ++mi) {
                uint32_t off = (uint32_t)(wm + mi * 16 + (lane & 15)) * LDSB
                             + ks * 32 + (lane >> 4) * 16;
                ldsm4(ah[mi], tb + 0 * TILE + off);
                if (use_lo) ldsm4(al[mi], tb + 1 * TILE + off);
            }
#pragma unroll
            for (int np = 0; np < 4; ++np) {
                uint32_t bf[4];
                uint32_t off = (uint32_t)(wn + np * 16 + (lane & 7)
                             + ((lane >> 4) & 1) * 8) * LDSB
                             + ks * 32 + ((lane >> 3) & 1) * 16;
                ldsm4(bf, tb + 2 * TILE + off);
#pragma unroll
                for (int mi = 0; mi < 2; ++mi)
#pragma unroll
                    for (int nj = 0; nj < 2; ++nj) {
                        float* a = acc[mi][2 * np + nj];
                        mma16816(a, ah[mi], &bf[nj * 2]);
                        if (use_lo) mma16816(a, al[mi], &bf[nj * 2]);
                    }
            }
        }
        if (++buf >= NSTG) buf -= NSTG;
    }

#pragma unroll
    for (int mi = 0; mi < 2; ++mi) {
        const int row = m0 + wm + mi * 16 + (lane >> 2);
#pragma unroll
        for (int ni = 0; ni < 8; ++ni) {
            const int col = n0 + wn + ni * 8 + (lane & 3) * 2;
            const float b0v = bias[col];
            const float b1v = bias[col + 1];
            float v0x = acc[mi][ni][0] + b0v;
            float v0y = acc[mi][ni][1] + b1v;
            float v1x = acc[mi][ni][2] + b0v;
            float v1y = acc[mi][ni][3] + b1v;
            if (SPLIT_OUT) {
                const bool isq = (col < C_DIM);
                if (isq) {   // pre-scale Q by 1/sqrt(D); exact (power of 2)
                    v0x *= 0.125f; v0y *= 0.125f;
                    v1x *= 0.125f; v1y *= 0.125f;
                }
                uint32_t h0, l0, h1, l1;
                split2h(v0x, v0y, h0, l0);
                split2h(v1x, v1y, h1, l1);
                const size_t o0 = (size_t)row * N + col;
                const size_t o1 = (size_t)(row + 8) * N + col;
                *(uint32_t*)(Ch + o0) = h0;
                *(uint32_t*)(Ch + o1) = h1;
                if (isq) {               // lo only ever read for Q columns
                    *(uint32_t*)(Cl + o0) = l0;
                    *(uint32_t*)(Cl + o1) = l1;
                }
            } else {
                float2 v0, v1;
                v0.x = v0x; v0.y = v0y;
                v1.x = v1x; v1.y = v1y;
                *(float2*)(C + (size_t)row * N + col)       = v0;
                *(float2*)(C + (size_t)(row + 8) * N + col) = v1;
            }
        }
    }
}

// ---------------------------------------------------------------------------
// HMMA causal flash attention (unchanged from R10). CTA: 128 q-rows x (b,h).
// Q pre-scaled; exps on MUFU; 3-stage K/V ring, one barrier/tile, 2 CTAs/SM.
// ---------------------------------------------------------------------------
#define FA_BQ   128
#define FA_BC   64
#define FA_LDB  144
#define FA_QH   0
#define FA_QL   (FA_BQ * FA_LDB)
#define FA_BUF  (2 * FA_BQ * FA_LDB)     // 36864: Q hi+lo
#define FA_TILE (FA_BC * FA_LDB)         // 9216
#define FA_BUFSZ (2 * FA_TILE)           // 18432 (Kh, Vh)
#define FA_NSTG 3
#define FA_SMEM (FA_BUF + FA_NSTG * FA_BUFSZ)  // 92160
#define NEG_BIG (-1e30f)

__global__ void __launch_bounds__(256, 2)
flash_mma(const __half* __restrict__ qh,
          const __half* __restrict__ ql,
          __half* __restrict__ ath,
          __half* __restrict__ atl)
{
    extern __shared__ char fsm[];
    const uint32_t sb = smem_u32(fsm);

    const int tid  = threadIdx.x;
    const int lane = tid & 31;
    const int wid  = tid >> 5;
    const int b = blockIdx.x >> 4;
    const int h = blockIdx.x & 15;
    const int yy = (int)gridDim.y - 1 - (int)blockIdx.y;   // heavy tiles first
    const int q0 = yy * FA_BQ;
    const int NT = 2 * (yy + 1);
    const int bT = b * T_DIM;
    const int hoff = h * D_DIM;

    auto load_tile = [&](int t, int bufi) {
        const int k0 = t * FA_BC;
        const int row = tid >> 2;
        const int ch2 = (tid & 3) * 2;
        const size_t rb = (size_t)(bT + k0 + row) * N_QKV + hoff;
        const uint32_t tb = sb + FA_BUF + bufi * FA_BUFSZ;
        const uint32_t d = tb + row * FA_LDB + ch2 * 16;
        const __half* skh = qh + rb + C_DIM;
        const __half* svh = qh + rb + 2 * C_DIM;
        cp16(d + 0 * FA_TILE,      skh + ch2 * 8);
        cp16(d + 0 * FA_TILE + 16, skh + ch2 * 8 + 8);
        cp16(d + 1 * FA_TILE,      svh + ch2 * 8);
        cp16(d + 1 * FA_TILE + 16, svh + ch2 * 8 + 8);
        CP_COMMIT();
    };

    // ---- issue Q tile load, then prefetch K/V tiles 0 & 1 ----
#pragma unroll
    for (int i = 0; i < 8; ++i) {
        int idx = tid + i * 256;
        int arr = idx >> 10;
        int wi  = idx & 1023;
        int row = wi >> 3;
        int ch  = wi & 7;
        const __half* src = (arr ? ql : qh)
            + (size_t)(bT + q0 + row) * N_QKV + hoff + ch * 8;
        cp16(sb + arr * (FA_BQ * FA_LDB) + row * FA_LDB + ch * 16, src);
    }
    CP_COMMIT();
    load_tile(0, 0);
    load_tile(1, 1);          // NT >= 2 always

    CP_WAIT(2);               // Q done; K/V tiles may still be in flight
    __syncthreads();

    uint32_t qfh[4][4], qfl[4][4];
#pragma unroll
    for (int ks = 0; ks < 4; ++ks) {
        uint32_t off = (uint32_t)(wid * 16 + (lane & 15)) * FA_LDB
                     + ks * 32 + (lane >> 4) * 16;
        ldsm4(qfh[ks], sb + FA_QH + off);
        ldsm4(qfl[ks], sb + FA_QL + off);
    }

    float o[8][4];
#pragma unroll
    for (int i = 0; i < 8; ++i)
#pragma unroll
        for (int j = 0; j < 4; ++j) o[i][j] = 0.0f;
    float m0 = NEG_BIG, m1 = NEG_BIG, l0 = 0.0f, l1 = 0.0f;
    const int qr  = q0 + wid * 16;
    const int qp0 = qr + (lane >> 2);
    const int qp1 = qp0 + 8;

    int buf = 0;
    for (int t = 0; t < NT; ++t) {
        if (t + 1 < NT) { CP_WAIT(1); } else { CP_WAIT(0); }
        __syncthreads();
        if (t + 2 < NT) {
            int nb = buf + 2; if (nb >= FA_NSTG) nb -= FA_NSTG;
            load_tile(t + 2, nb);
        }

        const int k0 = t * FA_BC;
        if (k0 <= qr + 15) {
            const uint32_t tb = sb + FA_BUF + buf * FA_BUFSZ;

            float s[8][4];
#pragma unroll
            for (int i = 0; i < 8; ++i)
#pragma unroll
                for (int j = 0; j < 4; ++j) s[i][j] = 0.0f;

#pragma unroll
            for (int ks = 0; ks < 4; ++ks) {
                uint32_t kh[4][4];
#pragma unroll
                for (int np = 0; np < 4; ++np) {
                    uint32_t off = (uint32_t)(np * 16 + (lane & 7)
                                 + ((lane >> 4) & 1) * 8) * FA_LDB
                                 + ks * 32 + ((lane >> 3) & 1) * 16;
                    ldsm4(kh[np], tb + 0 * FA_TILE + off);
                }
#pragma unroll
                for (int ni = 0; ni < 8; ++ni) {
                    const uint32_t* fh = &kh[ni >> 1][(ni & 1) * 2];
                    mma16816(s[ni], qfh[ks], fh);
                    mma16816(s[ni], qfl[ks], fh);
                }
            }

            // causal mask (scores already scaled: Q pre-scaled by 0.125)
            if (k0 + FA_BC - 1 > qr) {
#pragma unroll
                for (int ni = 0; ni < 8; ++ni) {
                    int kp = k0 + ni * 8 + 2 * (lane & 3);
                    if (kp     > qp0) s[ni][0] = NEG_BIG;
                    if (kp + 1 > qp0) s[ni][1] = NEG_BIG;
                    if (kp     > qp1) s[ni][2] = NEG_BIG;
                    if (kp + 1 > qp1) s[ni][3] = NEG_BIG;
                }
            }

            float mx0 = NEG_BIG, mx1 = NEG_BIG;
#pragma unroll
            for (int ni = 0; ni < 8; ++ni) {
                mx0 = fmaxf(mx0, fmaxf(s[ni][0], s[ni][1]));
                mx1 = fmaxf(mx1, fmaxf(s[ni][2], s[ni][3]));
            }
            mx0 = fmaxf(mx0, __shfl_xor_sync(0xffffffffu, mx0, 1));
            mx0 = fmaxf(mx0, __shfl_xor_sync(0xffffffffu, mx0, 2));
            mx1 = fmaxf(mx1, __shfl_xor_sync(0xffffffffu, mx1, 1));
            mx1 = fmaxf(mx1, __shfl_xor_sync(0xffffffffu, mx1, 2));
            const float m0n = fmaxf(m0, mx0);
            const float m1n = fmaxf(m1, mx1);
            const float c0 = __expf(m0 - m0n);
            const float c1 = __expf(m1 - m1n);
            l0 *= c0; l1 *= c1;
#pragma unroll
            for (int ni = 0; ni < 8; ++ni) {
                o[ni][0] *= c0; o[ni][1] *= c0;
                o[ni][2] *= c1; o[ni][3] *= c1;
            }
            m0 = m0n; m1 = m1n;

#pragma unroll
            for (int ni = 0; ni < 8; ++ni) {
                s[ni][0] = __expf(s[ni][0] - m0);
                s[ni][1] = __expf(s[ni][1] - m0);
                s[ni][2] = __expf(s[ni][2] - m1);
                s[ni][3] = __expf(s[ni][3] - m1);
                l0 += s[ni][0] + s[ni][1];
                l1 += s[ni][2] + s[ni][3];
            }

#pragma unroll
            for (int ks = 0; ks < 4; ++ks) {
                uint32_t pah[4], pal[4];
                split2h(s[2*ks][0],   s[2*ks][1],   pah[0], pal[0]);
                split2h(s[2*ks][2],   s[2*ks][3],   pah[1], pal[1]);
                split2h(s[2*ks+1][0], s[2*ks+1][1], pah[2], pal[2]);
                split2h(s[2*ks+1][2], s[2*ks+1][3], pah[3], pal[3]);

                uint32_t vh[4][4];
#pragma unroll
                for (int nd = 0; nd < 4; ++nd) {
                    uint32_t off = (uint32_t)(ks * 16 + (lane & 15)) * FA_LDB
                                 + nd * 32 + (lane >> 4) * 16;
                    ldsm4t(vh[nd], tb + 1 * FA_TILE + off);
                }
#pragma unroll
                for (int ni = 0; ni < 8; ++ni) {
                    const uint32_t* fh = &vh[ni >> 1][(ni & 1) * 2];
                    mma16816(o[ni], pah, fh);
                    mma16816(o[ni], pal, fh);
                }
            }
        }
        if (++buf >= FA_NSTG) buf -= FA_NSTG;
    }

    // ---- epilogue: l reduction + fp16 hi/lo split store ----
    float L0 = l0 + __shfl_xor_sync(0xffffffffu, l0, 1);
    L0 += __shfl_xor_sync(0xffffffffu, L0, 2);
    float L1 = l1 + __shfl_xor_sync(0xffffffffu, l1, 1);
    L1 += __shfl_xor_sync(0xffffffffu, L1, 2);
    const float i0 = 1.0f / L0;
    const float i1 = 1.0f / L1;

    const size_t r0o = (size_t)(bT + qp0) * C_DIM + hoff + 2 * (lane & 3);
    const size_t r1o = (size_t)(bT + qp1) * C_DIM + hoff + 2 * (lane & 3);
#pragma unroll
    for (int ni = 0; ni < 8; ++ni) {
        uint32_t hh, ll;
        split2h(o[ni][0] * i0, o[ni][1] * i0, hh, ll);
        *(uint32_t*)(ath + r0o + ni * 8) = hh;
        *(uint32_t*)(atl + r0o + ni * 8) = ll;
        split2h(o[ni][2] * i1, o[ni][3] * i1, hh, ll);
        *(uint32_t*)(ath + r1o + ni * 8) = hh;
        *(uint32_t*)(atl + r1o + ni * 8) = ll;
    }
}

// ---------------------------------------------------------------------------
// Launch
// ---------------------------------------------------------------------------
extern "C" void kernel_launch(void* const* d_in, const int* in_sizes, int n_in,
                              void* d_out, int out_size)
{
    const float* x      = (const float*)d_in[0];
    const float* w_attn = (const float*)d_in[1];
    const float* b_attn = (const float*)d_in[2];
    const float* w_proj = (const float*)d_in[3];
    const float* b_proj = (const float*)d_in[4];
    float* out = (float*)d_out;

    void *p_qh, *p_ql, *p_xh, *p_xl, *p_wt, *p_wpt, *p_ath, *p_atl;
    cudaGetSymbolAddress(&p_qh,  g_qkvh);
    cudaGetSymbolAddress(&p_ql,  g_qkvl);
    cudaGetSymbolAddress(&p_xh,  g_xh);
    cudaGetSymbolAddress(&p_xl,  g_xl);
    cudaGetSymbolAddress(&p_wt,  g_wt);
    cudaGetSymbolAddress(&p_wpt, g_wpt);
    cudaGetSymbolAddress(&p_ath, g_ath);
    cudaGetSymbolAddress(&p_atl, g_atl);

    cudaFuncSetAttribute(gemm_mma<true>,
                         cudaFuncAttributeMaxDynamicSharedMemorySize, GEMM_SMEM);
    cudaFuncSetAttribute(gemm_mma<false>,
                         cudaFuncAttributeMaxDynamicSharedMemorySize, GEMM_SMEM);
    cudaFuncSetAttribute(flash_mma,
                         cudaFuncAttributeMaxDynamicSharedMemorySize, FA_SMEM);

    // 1) split x -> fp16 hi/lo
    {
        int n = M_ROWS * C_DIM;
        k_split<<<n / 4 / 256, 256>>>(x, (__half*)p_xh, (__half*)p_xl, n);
    }
    // 2) transpose weights -> fp16 single
    {
        dim3 g(N_QKV / 32, C_DIM / 32);
        k_transpose_half<<<g, dim3(32, 8)>>>(w_attn, (__half*)p_wt, C_DIM, N_QKV);
    }
    {
        dim3 g(C_DIM / 32, C_DIM / 32);
        k_transpose_half<<<g, dim3(32, 8)>>>(w_proj, (__half*)p_wpt, C_DIM, C_DIM);
    }
    // 3) qkv = x @ w_attn + b_attn  (HMMA; Q 2-product, K/V 1-product)
    {
        dim3 grid(N_QKV / 128, M_ROWS / 128);
        gemm_mma<true><<<grid, 256, GEMM_SMEM>>>(
            (const __half*)p_xh, (const __half*)p_xl, (const __half*)p_wt,
            b_attn, nullptr,
            (__half*)p_qh, (__half*)p_ql, N_QKV, C_DIM);
    }
    // 4) causal MHA (HMMA flash, direct fp16 hi/lo output)
    {
        dim3 grid(B_DIM * H_DIM, T_DIM / FA_BQ);
        flash_mma<<<grid, 256, FA_SMEM>>>((const __half*)p_qh,
                                          (const __half*)p_ql,
                                          (__half*)p_ath,
                                          (__half*)p_atl);
    }
    // 5) out = att @ w_proj + b_proj (HMMA, fp32 output, 2-product)
    {
        dim3 grid(C_DIM / 128, M_ROWS / 128);
        gemm_mma<false><<<grid, 256, GEMM_SMEM>>>(
            (const __half*)p_ath, (const __half*)p_atl, (const __half*)p_wpt,
            b_proj, out, nullptr, nullptr, C_DIM, C_DIM);
    }
}

// round 12
// speedup vs baseline: 1.3189x; 1.1037x over previous
#include <cuda_runtime.h>
#include <cuda_fp16.h>
#include <math_constants.h>
#include <cstdint>

// ---------------------------------------------------------------------------
// Problem constants
// ---------------------------------------------------------------------------
#define B_DIM 4
#define T_DIM 2048
#define C_DIM 1024
#define H_DIM 16
#define D_DIM 64
#define M_ROWS (B_DIM * T_DIM)       // 8192
#define N_QKV  (3 * C_DIM)           // 3072

// ---------------------------------------------------------------------------
// Device scratch (allocation-free rule)
// ---------------------------------------------------------------------------
__device__ __half g_qkvh[(size_t)M_ROWS * N_QKV];   // qkv fp16 hi (Q scaled by 0.125*log2e)
__device__ __half g_qkvl[(size_t)M_ROWS * N_QKV];   // qkv fp16 lo (Q cols only)
__device__ __half g_xh[(size_t)M_ROWS * C_DIM];
__device__ __half g_xl[(size_t)M_ROWS * C_DIM];
__device__ __half g_wt[(size_t)N_QKV * C_DIM];      // w_attn^T fp16 [3072][1024]
__device__ __half g_wpt[(size_t)C_DIM * C_DIM];     // w_proj^T fp16 [1024][1024]
__device__ __half g_ath[(size_t)M_ROWS * C_DIM];
__device__ __half g_atl[(size_t)M_ROWS * C_DIM];

// ---------------------------------------------------------------------------
// Helpers
// ---------------------------------------------------------------------------
__device__ __forceinline__ uint32_t smem_u32(const void* p) {
    uint32_t a;
    asm("{ .reg .u64 t; cvta.to.shared.u64 t, %1; cvt.u32.u64 %0, t; }"
        : "=r"(a) : "l"(p));
    return a;
}

__device__ __forceinline__ void cp16(uint32_t dst, const void* src) {
    asm volatile("cp.async.cg.shared.global [%0], [%1], 16;"
                 :: "r"(dst), "l"(src));
}
#define CP_COMMIT() asm volatile("cp.async.commit_group;" ::: "memory")
#define CP_WAIT(n)  asm volatile("cp.async.wait_group %0;" :: "n"(n) : "memory")

__device__ __forceinline__ void ldsm4(uint32_t* r, uint32_t addr) {
    asm volatile("ldmatrix.sync.aligned.m8n8.x4.shared.b16 {%0,%1,%2,%3}, [%4];"
                 : "=r"(r[0]), "=r"(r[1]), "=r"(r[2]), "=r"(r[3]) : "r"(addr));
}

__device__ __forceinline__ void ldsm4t(uint32_t* r, uint32_t addr) {
    asm volatile("ldmatrix.sync.aligned.m8n8.x4.trans.shared.b16 {%0,%1,%2,%3}, [%4];"
                 : "=r"(r[0]), "=r"(r[1]), "=r"(r[2]), "=r"(r[3]) : "r"(addr));
}

__device__ __forceinline__ void mma16816(float* c, const uint32_t* a,
                                         const uint32_t* b) {
    asm volatile(
        "mma.sync.aligned.m16n8k16.row.col.f32.f16.f16.f32 "
        "{%0,%1,%2,%3}, {%4,%5,%6,%7}, {%8,%9}, {%0,%1,%2,%3};"
        : "+f"(c[0]), "+f"(c[1]), "+f"(c[2]), "+f"(c[3])
        : "r"(a[0]), "r"(a[1]), "r"(a[2]), "r"(a[3]), "r"(b[0]), "r"(b[1]));
}

// exp2 of a float pair -> packed fp16x2 via MUFU ex2.approx.f16x2
__device__ __forceinline__ uint32_t ex2h2(float x, float y) {
    __half2 h = __floats2half2_rn(x, y);
    uint32_t u = *reinterpret_cast<uint32_t*>(&h);
    uint32_t r;
    asm volatile("ex2.approx.f16x2 %0, %1;" : "=r"(r) : "r"(u));
    return r;
}

// exp2 fp32 (single MUFU op)
__device__ __forceinline__ float fexp2(float x) {
    float r;
    asm volatile("ex2.approx.f32 %0, %1;" : "=f"(r) : "f"(x));
    return r;
}

// Split a pair of floats into packed fp16 hi / lo uint32 fragments
__device__ __forceinline__ void split2h(float x, float y, uint32_t& h, uint32_t& l) {
    __half hx = __float2half(x);
    __half hy = __float2half(y);
    __half lx = __float2half(x - __half2float(hx));
    __half ly = __float2half(y - __half2float(hy));
    __half2 hp(hx, hy), lp(lx, ly);
    h = *reinterpret_cast<uint32_t*>(&hp);
    l = *reinterpret_cast<uint32_t*>(&lp);
}

// ---------------------------------------------------------------------------
// Prep kernels
// ---------------------------------------------------------------------------
__global__ void k_split(const float* __restrict__ in,
                        __half* __restrict__ hi,
                        __half* __restrict__ lo, int n)
{
    int i = (blockIdx.x * blockDim.x + threadIdx.x) * 4;
    if (i >= n) return;
    float4 v = *(const float4*)(in + i);
    float f[4] = {v.x, v.y, v.z, v.w};
    __half h[4], l[4];
#pragma unroll
    for (int j = 0; j < 4; ++j) {
        h[j] = __float2half(f[j]);
        l[j] = __float2half(f[j] - __half2float(h[j]));
    }
    *(__half2*)(hi + i)     = __half2(h[0], h[1]);
    *(__half2*)(hi + i + 2) = __half2(h[2], h[3]);
    *(__half2*)(lo + i)     = __half2(l[0], l[1]);
    *(__half2*)(lo + i + 2) = __half2(l[2], l[3]);
}

// W[K][N] row-major -> T[N][K] fp16 (single)
__global__ void k_transpose_half(const float* __restrict__ W,
                                 __half* __restrict__ T, int K, int N)
{
    __shared__ float tile[32][33];
    const int k0 = blockIdx.y * 32;
    const int n0 = blockIdx.x * 32;
    const int tx = threadIdx.x;
    const int ty = threadIdx.y;
#pragma unroll
    for (int r = 0; r < 4; ++r)
        tile[ty + r * 8][tx] = W[(size_t)(k0 + ty + r * 8) * N + n0 + tx];
    __syncthreads();
#pragma unroll
    for (int r = 0; r < 4; ++r) {
        float v = tile[tx][ty + r * 8];
        T[(size_t)(n0 + ty + r * 8) * K + k0 + tx] = __float2half(v);
    }
}

// ---------------------------------------------------------------------------
// HMMA GEMM: C = A @ Bt^T + bias.
// A = fp16 hi/lo 2-product for Q/proj columns; 1-product for K/V columns.
// Q columns pre-scaled by 0.125*log2(e) (scores land in log2 domain).
// 128x128 CTA tile, BK=32, 8 warps (32x64), 3-stage ring, 2 CTAs/SM.
// ---------------------------------------------------------------------------
#define BKC  32
#define LDSB 80                       // smem row stride bytes
#define TILE (128 * LDSB)             // 10240 per operand tile
#define STG  (3 * TILE)               // Ah, Al, B = 30720 per stage
#define NSTG 3
#define GEMM_SMEM (NSTG * STG)        // 92160 -> 2 CTAs/SM
#define QSCALE 0.18033688f            // 0.125 * log2(e)

template<bool SPLIT_OUT>
__global__ void __launch_bounds__(256, 2)
gemm_mma(const __half* __restrict__ Ah, const __half* __restrict__ Al,
         const __half* __restrict__ Bf,
         const float* __restrict__ bias, float* __restrict__ C,
         __half* __restrict__ Ch, __half* __restrict__ Cl,
         int N, int K)
{
    extern __shared__ char sm[];
    const uint32_t sbase = smem_u32(sm);

    const int tid  = threadIdx.x;
    const int lane = tid & 31;
    const int wid  = tid >> 5;
    const int m0 = blockIdx.y * 128;
    const int n0 = blockIdx.x * 128;
    const int wm = (wid & 3) * 32;        // 4 warps along M
    const int wn = (wid >> 2) * 64;       // 2 warps along N

    // CTA-uniform: K/V output columns are fp16-hi only -> skip the lo product
    const bool use_lo = (!SPLIT_OUT) || (n0 < C_DIM);

    float acc[2][8][4];
#pragma unroll
    for (int i = 0; i < 2; ++i)
#pragma unroll
        for (int j = 0; j < 8; ++j)
#pragma unroll
            for (int k = 0; k < 4; ++k) acc[i][j][k] = 0.0f;

    const int r0 = tid >> 2, c0 = tid & 3;
    const int r1 = r0 + 64;
    const __half* pAh0 = Ah + (size_t)(m0 + r0) * K + c0 * 8;
    const __half* pAh1 = Ah + (size_t)(m0 + r1) * K + c0 * 8;
    const __half* pAl0 = Al + (size_t)(m0 + r0) * K + c0 * 8;
    const __half* pAl1 = Al + (size_t)(m0 + r1) * K + c0 * 8;
    const __half* pB0  = Bf + (size_t)(n0 + r0) * K + c0 * 8;
    const __half* pB1  = Bf + (size_t)(n0 + r1) * K + c0 * 8;
    const uint32_t dA0 = (uint32_t)r0 * LDSB + (uint32_t)c0 * 16;
    const uint32_t dA1 = (uint32_t)r1 * LDSB + (uint32_t)c0 * 16;

    auto load_chunk = [&](int c, int buf) {
        const int koff = c * BKC;
        const uint32_t db = sbase + buf * STG;
        cp16(db + 0 * TILE + dA0, pAh0 + koff);
        cp16(db + 0 * TILE + dA1, pAh1 + koff);
        if (use_lo) {
            cp16(db + 1 * TILE + dA0, pAl0 + koff);
            cp16(db + 1 * TILE + dA1, pAl1 + koff);
        }
        cp16(db + 2 * TILE + dA0, pB0 + koff);
        cp16(db + 2 * TILE + dA1, pB1 + koff);
        CP_COMMIT();
    };

    const int NC = K / BKC;
    load_chunk(0, 0);
    load_chunk(1, 1);

    int buf = 0;
    for (int c = 0; c < NC; ++c) {
        if (c + 1 < NC) { CP_WAIT(1); } else { CP_WAIT(0); }
        __syncthreads();
        if (c + 2 < NC) {
            int nb = buf + 2; if (nb >= NSTG) nb -= NSTG;
            load_chunk(c + 2, nb);
        }

        const uint32_t tb = sbase + buf * STG;
#pragma unroll
        for (int ks = 0; ks < 2; ++ks) {
            uint32_t ah[2][4], al[2][4];
#pragma unroll
            for (int mi = 0; mi < 2; ++mi) {
                uint32_t off = (uint32_t)(wm + mi * 16 + (lane & 15)) * LDSB
                             + ks * 32 + (lane >> 4) * 16;
                ldsm4(ah[mi], tb + 0 * TILE + off);
                if (use_lo) ldsm4(al[mi], tb + 1 * TILE + off);
            }
#pragma unroll
            for (int np = 0; np < 4; ++np) {
                uint32_t bf[4];
                uint32_t off = (uint32_t)(wn + np * 16 + (lane & 7)
                             + ((lane >> 4) & 1) * 8) * LDSB
                             + ks * 32 + ((lane >> 3) & 1) * 16;
                ldsm4(bf, tb + 2 * TILE + off);
#pragma unroll
                for (int mi = 0; mi < 2; ++mi)
#pragma unroll
                    for (int nj = 0; nj < 2; ++nj) {
                        float* a = acc[mi][2 * np + nj];
                        mma16816(a, ah[mi], &bf[nj * 2]);
                        if (use_lo) mma16816(a, al[mi], &bf[nj * 2]);
                    }
            }
        }
        if (++buf >= NSTG) buf -= NSTG;
    }

#pragma unroll
    for (int mi = 0; mi < 2; ++mi) {
        const int row = m0 + wm + mi * 16 + (lane >> 2);
#pragma unroll
        for (int ni = 0; ni < 8; ++ni) {
            const int col = n0 + wn + ni * 8 + (lane & 3) * 2;
            const float b0v = bias[col];
            const float b1v = bias[col + 1];
            float v0x = acc[mi][ni][0] + b0v;
            float v0y = acc[mi][ni][1] + b1v;
            float v1x = acc[mi][ni][2] + b0v;
            float v1y = acc[mi][ni][3] + b1v;
            if (SPLIT_OUT) {
                const bool isq = (col < C_DIM);
                if (isq) {   // scale Q by 1/sqrt(D) * log2(e)
                    v0x *= QSCALE; v0y *= QSCALE;
                    v1x *= QSCALE; v1y *= QSCALE;
                }
                uint32_t h0, l0, h1, l1;
                split2h(v0x, v0y, h0, l0);
                split2h(v1x, v1y, h1, l1);
                const size_t o0 = (size_t)row * N + col;
                const size_t o1 = (size_t)(row + 8) * N + col;
                *(uint32_t*)(Ch + o0) = h0;
                *(uint32_t*)(Ch + o1) = h1;
                if (isq) {               // lo only ever read for Q columns
                    *(uint32_t*)(Cl + o0) = l0;
                    *(uint32_t*)(Cl + o1) = l1;
                }
            } else {
                float2 v0, v1;
                v0.x = v0x; v0.y = v0y;
                v1.x = v1x; v1.y = v1y;
                *(float2*)(C + (size_t)row * N + col)       = v0;
                *(float2*)(C + (size_t)(row + 8) * N + col) = v1;
            }
        }
    }
}

// ---------------------------------------------------------------------------
// HMMA causal flash attention, log2-domain softmax.
// Scores arrive in log2 units (Q pre-scaled by 0.125*log2e).
// P generated by ex2.approx.f16x2 (fp16, single PV product).
// Row sums l computed by a ones-column MMA (no shfl reduction).
// 3-stage K/V ring, one barrier/tile, 2 CTAs/SM.
// ---------------------------------------------------------------------------
#define FA_BQ   128
#define FA_BC   64
#define FA_LDB  144
#define FA_QH   0
#define FA_QL   (FA_BQ * FA_LDB)
#define FA_BUF  (2 * FA_BQ * FA_LDB)     // 36864: Q hi+lo
#define FA_TILE (FA_BC * FA_LDB)         // 9216
#define FA_BUFSZ (2 * FA_TILE)           // 18432 (Kh, Vh)
#define FA_NSTG 3
#define FA_SMEM (FA_BUF + FA_NSTG * FA_BUFSZ)  // 92160
#define NEG_BIG (-1e30f)
#define ONE_H2  0x3C003C00u              // half2(1.0, 1.0)

__global__ void __launch_bounds__(256, 2)
flash_mma(const __half* __restrict__ qh,
          const __half* __restrict__ ql,
          __half* __restrict__ ath,
          __half* __restrict__ atl)
{
    extern __shared__ char fsm[];
    const uint32_t sb = smem_u32(fsm);

    const int tid  = threadIdx.x;
    const int lane = tid & 31;
    const int wid  = tid >> 5;
    const int b = blockIdx.x >> 4;
    const int h = blockIdx.x & 15;
    const int yy = (int)gridDim.y - 1 - (int)blockIdx.y;   // heavy tiles first
    const int q0 = yy * FA_BQ;
    const int NT = 2 * (yy + 1);
    const int bT = b * T_DIM;
    const int hoff = h * D_DIM;

    auto load_tile = [&](int t, int bufi) {
        const int k0 = t * FA_BC;
        const int row = tid >> 2;
        const int ch2 = (tid & 3) * 2;
        const size_t rb = (size_t)(bT + k0 + row) * N_QKV + hoff;
        const uint32_t tb = sb + FA_BUF + bufi * FA_BUFSZ;
        const uint32_t d = tb + row * FA_LDB + ch2 * 16;
        const __half* skh = qh + rb + C_DIM;
        const __half* svh = qh + rb + 2 * C_DIM;
        cp16(d + 0 * FA_TILE,      skh + ch2 * 8);
        cp16(d + 0 * FA_TILE + 16, skh + ch2 * 8 + 8);
        cp16(d + 1 * FA_TILE,      svh + ch2 * 8);
        cp16(d + 1 * FA_TILE + 16, svh + ch2 * 8 + 8);
        CP_COMMIT();
    };

    // ---- issue Q tile load, then prefetch K/V tiles 0 & 1 ----
#pragma unroll
    for (int i = 0; i < 8; ++i) {
        int idx = tid + i * 256;
        int arr = idx >> 10;
        int wi  = idx & 1023;
        int row = wi >> 3;
        int ch  = wi & 7;
        const __half* src = (arr ? ql : qh)
            + (size_t)(bT + q0 + row) * N_QKV + hoff + ch * 8;
        cp16(sb + arr * (FA_BQ * FA_LDB) + row * FA_LDB + ch * 16, src);
    }
    CP_COMMIT();
    load_tile(0, 0);
    load_tile(1, 1);          // NT >= 2 always

    CP_WAIT(2);               // Q done; K/V tiles may still be in flight
    __syncthreads();

    uint32_t qfh[4][4], qfl[4][4];
#pragma unroll
    for (int ks = 0; ks < 4; ++ks) {
        uint32_t off = (uint32_t)(wid * 16 + (lane & 15)) * FA_LDB
                     + ks * 32 + (lane >> 4) * 16;
        ldsm4(qfh[ks], sb + FA_QH + off);
        ldsm4(qfl[ks], sb + FA_QL + off);
    }

    float o[8][4];
#pragma unroll
    for (int i = 0; i < 8; ++i)
#pragma unroll
        for (int j = 0; j < 4; ++j) o[i][j] = 0.0f;
    float la[4] = {0.0f, 0.0f, 0.0f, 0.0f};       // l via ones-MMA
    float m0 = NEG_BIG, m1 = NEG_BIG;
    const int qr  = q0 + wid * 16;
    const int qp0 = qr + (lane >> 2);
    const int qp1 = qp0 + 8;
    const uint32_t ones[2] = {ONE_H2, ONE_H2};

    int buf = 0;
    for (int t = 0; t < NT; ++t) {
        if (t + 1 < NT) { CP_WAIT(1); } else { CP_WAIT(0); }
        __syncthreads();
        if (t + 2 < NT) {
            int nb = buf + 2; if (nb >= FA_NSTG) nb -= FA_NSTG;
            load_tile(t + 2, nb);
        }

        const int k0 = t * FA_BC;
        if (k0 <= qr + 15) {
            const uint32_t tb = sb + FA_BUF + buf * FA_BUFSZ;

            float s[8][4];
#pragma unroll
            for (int i = 0; i < 8; ++i)
#pragma unroll
                for (int j = 0; j < 4; ++j) s[i][j] = 0.0f;

#pragma unroll
            for (int ks = 0; ks < 4; ++ks) {
                uint32_t kh[4][4];
#pragma unroll
                for (int np = 0; np < 4; ++np) {
                    uint32_t off = (uint32_t)(np * 16 + (lane & 7)
                                 + ((lane >> 4) & 1) * 8) * FA_LDB
                                 + ks * 32 + ((lane >> 3) & 1) * 16;
                    ldsm4(kh[np], tb + 0 * FA_TILE + off);
                }
#pragma unroll
                for (int ni = 0; ni < 8; ++ni) {
                    const uint32_t* fh = &kh[ni >> 1][(ni & 1) * 2];
                    mma16816(s[ni], qfh[ks], fh);
                    mma16816(s[ni], qfl[ks], fh);
                }
            }

            // causal mask (s already in log2 units)
            if (k0 + FA_BC - 1 > qr) {
#pragma unroll
                for (int ni = 0; ni < 8; ++ni) {
                    int kp = k0 + ni * 8 + 2 * (lane & 3);
                    if (kp     > qp0) s[ni][0] = NEG_BIG;
                    if (kp + 1 > qp0) s[ni][1] = NEG_BIG;
                    if (kp     > qp1) s[ni][2] = NEG_BIG;
                    if (kp + 1 > qp1) s[ni][3] = NEG_BIG;
                }
            }

            float mx0 = NEG_BIG, mx1 = NEG_BIG;
#pragma unroll
            for (int ni = 0; ni < 8; ++ni) {
                mx0 = fmaxf(mx0, fmaxf(s[ni][0], s[ni][1]));
                mx1 = fmaxf(mx1, fmaxf(s[ni][2], s[ni][3]));
            }
            mx0 = fmaxf(mx0, __shfl_xor_sync(0xffffffffu, mx0, 1));
            mx0 = fmaxf(mx0, __shfl_xor_sync(0xffffffffu, mx0, 2));
            mx1 = fmaxf(mx1, __shfl_xor_sync(0xffffffffu, mx1, 1));
            mx1 = fmaxf(mx1, __shfl_xor_sync(0xffffffffu, mx1, 2));
            const float m0n = fmaxf(m0, mx0);
            const float m1n = fmaxf(m1, mx1);
            const float c0 = fexp2(m0 - m0n);     // 0 on first tile
            const float c1 = fexp2(m1 - m1n);
            la[0] *= c0; la[2] *= c1;
#pragma unroll
            for (int ni = 0; ni < 8; ++ni) {
                o[ni][0] *= c0; o[ni][1] *= c0;
                o[ni][2] *= c1; o[ni][3] *= c1;
            }
            m0 = m0n; m1 = m1n;

            // P = exp2(s - m) as fp16 fragments; l += P @ 1; O += P V
#pragma unroll
            for (int ks = 0; ks < 4; ++ks) {
                uint32_t pa[4];
                pa[0] = ex2h2(s[2*ks][0]   - m0, s[2*ks][1]   - m0);
                pa[1] = ex2h2(s[2*ks][2]   - m1, s[2*ks][3]   - m1);
                pa[2] = ex2h2(s[2*ks+1][0] - m0, s[2*ks+1][1] - m0);
                pa[3] = ex2h2(s[2*ks+1][2] - m1, s[2*ks+1][3] - m1);

                mma16816(la, pa, ones);           // row sums

                uint32_t vh[4][4];
#pragma unroll
                for (int nd = 0; nd < 4; ++nd) {
                    uint32_t off = (uint32_t)(ks * 16 + (lane & 15)) * FA_LDB
                                 + nd * 32 + (lane >> 4) * 16;
                    ldsm4t(vh[nd], tb + 1 * FA_TILE + off);
                }
#pragma unroll
                for (int ni = 0; ni < 8; ++ni) {
                    const uint32_t* fh = &vh[ni >> 1][(ni & 1) * 2];
                    mma16816(o[ni], pa, fh);
                }
            }
        }
        if (++buf >= FA_NSTG) buf -= FA_NSTG;
    }

    // ---- epilogue: normalize + fp16 hi/lo split store ----
    const float i0 = 1.0f / la[0];
    const float i1 = 1.0f / la[2];

    const size_t r0o = (size_t)(bT + qp0) * C_DIM + hoff + 2 * (lane & 3);
    const size_t r1o = (size_t)(bT + qp1) * C_DIM + hoff + 2 * (lane & 3);
#pragma unroll
    for (int ni = 0; ni < 8; ++ni) {
        uint32_t hh, ll;
        split2h(o[ni][0] * i0, o[ni][1] * i0, hh, ll);
        *(uint32_t*)(ath + r0o + ni * 8) = hh;
        *(uint32_t*)(atl + r0o + ni * 8) = ll;
        split2h(o[ni][2] * i1, o[ni][3] * i1, hh, ll);
        *(uint32_t*)(ath + r1o + ni * 8) = hh;
        *(uint32_t*)(atl + r1o + ni * 8) = ll;
    }
}

// ---------------------------------------------------------------------------
// Launch
// ---------------------------------------------------------------------------
extern "C" void kernel_launch(void* const* d_in, const int* in_sizes, int n_in,
                              void* d_out, int out_size)
{
    const float* x      = (const float*)d_in[0];
    const float* w_attn = (const float*)d_in[1];
    const float* b_attn = (const float*)d_in[2];
    const float* w_proj = (const float*)d_in[3];
    const float* b_proj = (const float*)d_in[4];
    float* out = (float*)d_out;

    void *p_qh, *p_ql, *p_xh, *p_xl, *p_wt, *p_wpt, *p_ath, *p_atl;
    cudaGetSymbolAddress(&p_qh,  g_qkvh);
    cudaGetSymbolAddress(&p_ql,  g_qkvl);
    cudaGetSymbolAddress(&p_xh,  g_xh);
    cudaGetSymbolAddress(&p_xl,  g_xl);
    cudaGetSymbolAddress(&p_wt,  g_wt);
    cudaGetSymbolAddress(&p_wpt, g_wpt);
    cudaGetSymbolAddress(&p_ath, g_ath);
    cudaGetSymbolAddress(&p_atl, g_atl);

    cudaFuncSetAttribute(gemm_mma<true>,
                         cudaFuncAttributeMaxDynamicSharedMemorySize, GEMM_SMEM);
    cudaFuncSetAttribute(gemm_mma<false>,
                         cudaFuncAttributeMaxDynamicSharedMemorySize, GEMM_SMEM);
    cudaFuncSetAttribute(flash_mma,
                         cudaFuncAttributeMaxDynamicSharedMemorySize, FA_SMEM);

    // 1) split x -> fp16 hi/lo
    {
        int n = M_ROWS * C_DIM;
        k_split<<<n / 4 / 256, 256>>>(x, (__half*)p_xh, (__half*)p_xl, n);
    }
    // 2) transpose weights -> fp16 single
    {
        dim3 g(N_QKV / 32, C_DIM / 32);
        k_transpose_half<<<g, dim3(32, 8)>>>(w_attn, (__half*)p_wt, C_DIM, N_QKV);
    }
    {
        dim3 g(C_DIM / 32, C_DIM / 32);
        k_transpose_half<<<g, dim3(32, 8)>>>(w_proj, (__half*)p_wpt, C_DIM, C_DIM);
    }
    // 3) qkv = x @ w_attn + b_attn  (HMMA; Q 2-product+log2e scale, K/V 1-product)
    {
        dim3 grid(N_QKV / 128, M_ROWS / 128);
        gemm_mma<true><<<grid, 256, GEMM_SMEM>>>(
            (const __half*)p_xh, (const __half*)p_xl, (const __half*)p_wt,
            b_attn, nullptr,
            (__half*)p_qh, (__half*)p_ql, N_QKV, C_DIM);
    }
    // 4) causal MHA (HMMA flash, log2-domain softmax, fp16 hi/lo output)
    {
        dim3 grid(B_DIM * H_DIM, T_DIM / FA_BQ);
        flash_mma<<<grid, 256, FA_SMEM>>>((const __half*)p_qh,
                                          (const __half*)p_ql,
                                          (__half*)p_ath,
                                          (__half*)p_atl);
    }
    // 5) out = att @ w_proj + b_proj (HMMA, fp32 output, 2-product)
    {
        dim3 grid(C_DIM / 128, M_ROWS / 128);
        gemm_mma<false><<<grid, 256, GEMM_SMEM>>>(
            (const __half*)p_ath, (const __half*)p_atl, (const __half*)p_wpt,
            b_proj, out, nullptr, nullptr, C_DIM, C_DIM);
    }
}

// round 13
// speedup vs baseline: 1.6805x; 1.2742x over previous
#include <cuda_runtime.h>
#include <cuda_fp16.h>
#include <math_constants.h>
#include <cstdint>

// ---------------------------------------------------------------------------
// Problem constants
// ---------------------------------------------------------------------------
#define B_DIM 4
#define T_DIM 2048
#define C_DIM 1024
#define H_DIM 16
#define D_DIM 64
#define M_ROWS (B_DIM * T_DIM)       // 8192
#define N_QKV  (3 * C_DIM)           // 3072

// ---------------------------------------------------------------------------
// Device scratch (allocation-free rule)
// ---------------------------------------------------------------------------
__device__ __half g_qkvh[(size_t)M_ROWS * N_QKV];   // qkv fp16 (Q scaled by 0.125*log2e)
__device__ __half g_xh[(size_t)M_ROWS * C_DIM];     // x fp16
__device__ __half g_wt[(size_t)N_QKV * C_DIM];      // w_attn^T fp16 [3072][1024]
__device__ __half g_wpt[(size_t)C_DIM * C_DIM];     // w_proj^T fp16 [1024][1024]
__device__ __half g_ath[(size_t)M_ROWS * C_DIM];    // attn out hi
__device__ __half g_atl[(size_t)M_ROWS * C_DIM];    // attn out lo

// ---------------------------------------------------------------------------
// Helpers
// ---------------------------------------------------------------------------
__device__ __forceinline__ uint32_t smem_u32(const void* p) {
    uint32_t a;
    asm("{ .reg .u64 t; cvta.to.shared.u64 t, %1; cvt.u32.u64 %0, t; }"
        : "=r"(a) : "l"(p));
    return a;
}

__device__ __forceinline__ void cp16(uint32_t dst, const void* src) {
    asm volatile("cp.async.cg.shared.global [%0], [%1], 16;"
                 :: "r"(dst), "l"(src));
}
#define CP_COMMIT() asm volatile("cp.async.commit_group;" ::: "memory")
#define CP_WAIT(n)  asm volatile("cp.async.wait_group %0;" :: "n"(n) : "memory")

__device__ __forceinline__ void ldsm4(uint32_t* r, uint32_t addr) {
    asm volatile("ldmatrix.sync.aligned.m8n8.x4.shared.b16 {%0,%1,%2,%3}, [%4];"
                 : "=r"(r[0]), "=r"(r[1]), "=r"(r[2]), "=r"(r[3]) : "r"(addr));
}

__device__ __forceinline__ void ldsm4t(uint32_t* r, uint32_t addr) {
    asm volatile("ldmatrix.sync.aligned.m8n8.x4.trans.shared.b16 {%0,%1,%2,%3}, [%4];"
                 : "=r"(r[0]), "=r"(r[1]), "=r"(r[2]), "=r"(r[3]) : "r"(addr));
}

__device__ __forceinline__ void mma16816(float* c, const uint32_t* a,
                                         const uint32_t* b) {
    asm volatile(
        "mma.sync.aligned.m16n8k16.row.col.f32.f16.f16.f32 "
        "{%0,%1,%2,%3}, {%4,%5,%6,%7}, {%8,%9}, {%0,%1,%2,%3};"
        : "+f"(c[0]), "+f"(c[1]), "+f"(c[2]), "+f"(c[3])
        : "r"(a[0]), "r"(a[1]), "r"(a[2]), "r"(a[3]), "r"(b[0]), "r"(b[1]));
}

// exp2 of a float pair -> packed fp16x2 via MUFU ex2.approx.f16x2
__device__ __forceinline__ uint32_t ex2h2(float x, float y) {
    __half2 h = __floats2half2_rn(x, y);
    uint32_t u = *reinterpret_cast<uint32_t*>(&h);
    uint32_t r;
    asm volatile("ex2.approx.f16x2 %0, %1;" : "=r"(r) : "r"(u));
    return r;
}

// exp2 fp32 (single MUFU op)
__device__ __forceinline__ float fexp2(float x) {
    float r;
    asm volatile("ex2.approx.f32 %0, %1;" : "=f"(r) : "f"(x));
    return r;
}

// Split a pair of floats into packed fp16 hi / lo uint32 fragments
__device__ __forceinline__ void split2h(float x, float y, uint32_t& h, uint32_t& l) {
    __half hx = __float2half(x);
    __half hy = __float2half(y);
    __half lx = __float2half(x - __half2float(hx));
    __half ly = __float2half(y - __half2float(hy));
    __half2 hp(hx, hy), lp(lx, ly);
    h = *reinterpret_cast<uint32_t*>(&hp);
    l = *reinterpret_cast<uint32_t*>(&lp);
}

// ---------------------------------------------------------------------------
// Prep kernels
// ---------------------------------------------------------------------------
__global__ void k_half(const float* __restrict__ in,
                       __half* __restrict__ outp, int n)
{
    int i = (blockIdx.x * blockDim.x + threadIdx.x) * 4;
    if (i >= n) return;
    float4 v = *(const float4*)(in + i);
    *(__half2*)(outp + i)     = __floats2half2_rn(v.x, v.y);
    *(__half2*)(outp + i + 2) = __floats2half2_rn(v.z, v.w);
}

// W[K][N] row-major -> T[N][K] fp16 (single)
__global__ void k_transpose_half(const float* __restrict__ W,
                                 __half* __restrict__ T, int K, int N)
{
    __shared__ float tile[32][33];
    const int k0 = blockIdx.y * 32;
    const int n0 = blockIdx.x * 32;
    const int tx = threadIdx.x;
    const int ty = threadIdx.y;
#pragma unroll
    for (int r = 0; r < 4; ++r)
        tile[ty + r * 8][tx] = W[(size_t)(k0 + ty + r * 8) * N + n0 + tx];
    __syncthreads();
#pragma unroll
    for (int r = 0; r < 4; ++r) {
        float v = tile[tx][ty + r * 8];
        T[(size_t)(n0 + ty + r * 8) * K + k0 + tx] = __float2half(v);
    }
}

// ---------------------------------------------------------------------------
// Common GEMM geometry
// ---------------------------------------------------------------------------
#define BKC  32
#define LDSB 80                       // smem row stride bytes
#define TILE (128 * LDSB)             // 10240 per operand tile
#define QSCALE 0.18033688f            // 0.125 * log2(e)

// ---------------------------------------------------------------------------
// QKV GEMM: C[fp16] = A[fp16] @ Bt^T + bias. Pure 1-product.
// Q columns (col < C_DIM) scaled by 0.125*log2e.
// 128x128 CTA tile, BK=32, 8 warps (32x64), 3-stage ring, 2 CTAs/SM.
// ---------------------------------------------------------------------------
#define QSTG  (2 * TILE)              // A, B = 20480 per stage
#define QNSTG 3
#define QKV_SMEM (QNSTG * QSTG)       // 61440 -> 2 CTAs/SM

__global__ void __launch_bounds__(256, 2)
gemm_qkv(const __half* __restrict__ A, const __half* __restrict__ Bf,
         const float* __restrict__ bias, __half* __restrict__ Ch,
         int N, int K)
{
    extern __shared__ char sm[];
    const uint32_t sbase = smem_u32(sm);

    const int tid  = threadIdx.x;
    const int lane = tid & 31;
    const int wid  = tid >> 5;
    const int m0 = blockIdx.y * 128;
    const int n0 = blockIdx.x * 128;
    const int wm = (wid & 3) * 32;
    const int wn = (wid >> 2) * 64;

    float acc[2][8][4];
#pragma unroll
    for (int i = 0; i < 2; ++i)
#pragma unroll
        for (int j = 0; j < 8; ++j)
#pragma unroll
            for (int k = 0; k < 4; ++k) acc[i][j][k] = 0.0f;

    const int r0 = tid >> 2, c0 = tid & 3;
    const int r1 = r0 + 64;
    const __half* pA0 = A + (size_t)(m0 + r0) * K + c0 * 8;
    const __half* pA1 = A + (size_t)(m0 + r1) * K + c0 * 8;
    const __half* pB0 = Bf + (size_t)(n0 + r0) * K + c0 * 8;
    const __half* pB1 = Bf + (size_t)(n0 + r1) * K + c0 * 8;
    const uint32_t dA0 = (uint32_t)r0 * LDSB + (uint32_t)c0 * 16;
    const uint32_t dA1 = (uint32_t)r1 * LDSB + (uint32_t)c0 * 16;

    auto load_chunk = [&](int c, int buf) {
        const int koff = c * BKC;
        const uint32_t db = sbase + buf * QSTG;
        cp16(db + dA0, pA0 + koff);
        cp16(db + dA1, pA1 + koff);
        cp16(db + TILE + dA0, pB0 + koff);
        cp16(db + TILE + dA1, pB1 + koff);
        CP_COMMIT();
    };

    const int NC = K / BKC;
    load_chunk(0, 0);
    load_chunk(1, 1);

    int buf = 0;
    for (int c = 0; c < NC; ++c) {
        if (c + 1 < NC) { CP_WAIT(1); } else { CP_WAIT(0); }
        __syncthreads();
        if (c + 2 < NC) {
            int nb = buf + 2; if (nb >= QNSTG) nb -= QNSTG;
            load_chunk(c + 2, nb);
        }

        const uint32_t tb = sbase + buf * QSTG;
#pragma unroll
        for (int ks = 0; ks < 2; ++ks) {
            uint32_t ah[2][4];
#pragma unroll
            for (int mi = 0; mi < 2; ++mi) {
                uint32_t off = (uint32_t)(wm + mi * 16 + (lane & 15)) * LDSB
                             + ks * 32 + (lane >> 4) * 16;
                ldsm4(ah[mi], tb + off);
            }
#pragma unroll
            for (int np = 0; np < 4; ++np) {
                uint32_t bf[4];
                uint32_t off = (uint32_t)(wn + np * 16 + (lane & 7)
                             + ((lane >> 4) & 1) * 8) * LDSB
                             + ks * 32 + ((lane >> 3) & 1) * 16;
                ldsm4(bf, tb + TILE + off);
#pragma unroll
                for (int mi = 0; mi < 2; ++mi)
#pragma unroll
                    for (int nj = 0; nj < 2; ++nj)
                        mma16816(acc[mi][2 * np + nj], ah[mi], &bf[nj * 2]);
            }
        }
        if (++buf >= QNSTG) buf -= QNSTG;
    }

#pragma unroll
    for (int mi = 0; mi < 2; ++mi) {
        const int row = m0 + wm + mi * 16 + (lane >> 2);
#pragma unroll
        for (int ni = 0; ni < 8; ++ni) {
            const int col = n0 + wn + ni * 8 + (lane & 3) * 2;
            float v0x = acc[mi][ni][0] + bias[col];
            float v0y = acc[mi][ni][1] + bias[col + 1];
            float v1x = acc[mi][ni][2] + bias[col];
            float v1y = acc[mi][ni][3] + bias[col + 1];
            if (col < C_DIM) {     // Q: scale by 1/sqrt(D)*log2e
                v0x *= QSCALE; v0y *= QSCALE;
                v1x *= QSCALE; v1y *= QSCALE;
            }
            __half2 h0 = __floats2half2_rn(v0x, v0y);
            __half2 h1 = __floats2half2_rn(v1x, v1y);
            *(__half2*)(Ch + (size_t)row * N + col)       = h0;
            *(__half2*)(Ch + (size_t)(row + 8) * N + col) = h1;
        }
    }
}

// ---------------------------------------------------------------------------
// Proj GEMM: C[fp32] = (Ah+Al) @ Bt^T + bias. 2-product (precision anchor).
// Same geometry; 3-stage ring with Ah, Al, B (30720/stage), 2 CTAs/SM.
// ---------------------------------------------------------------------------
#define PSTG  (3 * TILE)              // 30720 per stage
#define PNSTG 3
#define PROJ_SMEM (PNSTG * PSTG)      // 92160

__global__ void __launch_bounds__(256, 2)
gemm_proj(const __half* __restrict__ Ah, const __half* __restrict__ Al,
          const __half* __restrict__ Bf,
          const float* __restrict__ bias, float* __restrict__ C,
          int N, int K)
{
    extern __shared__ char sm[];
    const uint32_t sbase = smem_u32(sm);

    const int tid  = threadIdx.x;
    const int lane = tid & 31;
    const int wid  = tid >> 5;
    const int m0 = blockIdx.y * 128;
    const int n0 = blockIdx.x * 128;
    const int wm = (wid & 3) * 32;
    const int wn = (wid >> 2) * 64;

    float acc[2][8][4];
#pragma unroll
    for (int i = 0; i < 2; ++i)
#pragma unroll
        for (int j = 0; j < 8; ++j)
#pragma unroll
            for (int k = 0; k < 4; ++k) acc[i][j][k] = 0.0f;

    const int r0 = tid >> 2, c0 = tid & 3;
    const int r1 = r0 + 64;
    const __half* pAh0 = Ah + (size_t)(m0 + r0) * K + c0 * 8;
    const __half* pAh1 = Ah + (size_t)(m0 + r1) * K + c0 * 8;
    const __half* pAl0 = Al + (size_t)(m0 + r0) * K + c0 * 8;
    const __half* pAl1 = Al + (size_t)(m0 + r1) * K + c0 * 8;
    const __half* pB0  = Bf + (size_t)(n0 + r0) * K + c0 * 8;
    const __half* pB1  = Bf + (size_t)(n0 + r1) * K + c0 * 8;
    const uint32_t dA0 = (uint32_t)r0 * LDSB + (uint32_t)c0 * 16;
    const uint32_t dA1 = (uint32_t)r1 * LDSB + (uint32_t)c0 * 16;

    auto load_chunk = [&](int c, int buf) {
        const int koff = c * BKC;
        const uint32_t db = sbase + buf * PSTG;
        cp16(db + 0 * TILE + dA0, pAh0 + koff);
        cp16(db + 0 * TILE + dA1, pAh1 + koff);
        cp16(db + 1 * TILE + dA0, pAl0 + koff);
        cp16(db + 1 * TILE + dA1, pAl1 + koff);
        cp16(db + 2 * TILE + dA0, pB0 + koff);
        cp16(db + 2 * TILE + dA1, pB1 + koff);
        CP_COMMIT();
    };

    const int NC = K / BKC;
    load_chunk(0, 0);
    load_chunk(1, 1);

    int buf = 0;
    for (int c = 0; c < NC; ++c) {
        if (c + 1 < NC) { CP_WAIT(1); } else { CP_WAIT(0); }
        __syncthreads();
        if (c + 2 < NC) {
            int nb = buf + 2; if (nb >= PNSTG) nb -= PNSTG;
            load_chunk(c + 2, nb);
        }

        const uint32_t tb = sbase + buf * PSTG;
#pragma unroll
        for (int ks = 0; ks < 2; ++ks) {
            uint32_t ah[2][4], al[2][4];
#pragma unroll
            for (int mi = 0; mi < 2; ++mi) {
                uint32_t off = (uint32_t)(wm + mi * 16 + (lane & 15)) * LDSB
                             + ks * 32 + (lane >> 4) * 16;
                ldsm4(ah[mi], tb + 0 * TILE + off);
                ldsm4(al[mi], tb + 1 * TILE + off);
            }
#pragma unroll
            for (int np = 0; np < 4; ++np) {
                uint32_t bf[4];
                uint32_t off = (uint32_t)(wn + np * 16 + (lane & 7)
                             + ((lane >> 4) & 1) * 8) * LDSB
                             + ks * 32 + ((lane >> 3) & 1) * 16;
                ldsm4(bf, tb + 2 * TILE + off);
#pragma unroll
                for (int mi = 0; mi < 2; ++mi)
#pragma unroll
                    for (int nj = 0; nj < 2; ++nj) {
                        float* a = acc[mi][2 * np + nj];
                        mma16816(a, ah[mi], &bf[nj * 2]);
                        mma16816(a, al[mi], &bf[nj * 2]);
                    }
            }
        }
        if (++buf >= PNSTG) buf -= PNSTG;
    }

#pragma unroll
    for (int mi = 0; mi < 2; ++mi) {
        const int row = m0 + wm + mi * 16 + (lane >> 2);
#pragma unroll
        for (int ni = 0; ni < 8; ++ni) {
            const int col = n0 + wn + ni * 8 + (lane & 3) * 2;
            float2 v0, v1;
            v0.x = acc[mi][ni][0] + bias[col];
            v0.y = acc[mi][ni][1] + bias[col + 1];
            v1.x = acc[mi][ni][2] + bias[col];
            v1.y = acc[mi][ni][3] + bias[col + 1];
            *(float2*)(C + (size_t)row * N + col)       = v0;
            *(float2*)(C + (size_t)(row + 8) * N + col) = v1;
        }
    }
}

// ---------------------------------------------------------------------------
// HMMA causal flash attention, log2-domain softmax, single-fp16 Q.
// P via ex2.approx.f16x2; row sums via ones-MMA.
// 3-stage K/V ring, one barrier/tile, 2 CTAs/SM.
// ---------------------------------------------------------------------------
#define FA_BQ   128
#define FA_BC   64
#define FA_LDB  144
#define FA_BUF  (FA_BQ * FA_LDB)         // 18432: Q (single)
#define FA_TILE (FA_BC * FA_LDB)         // 9216
#define FA_BUFSZ (2 * FA_TILE)           // 18432 (Kh, Vh)
#define FA_NSTG 3
#define FA_SMEM (FA_BUF + FA_NSTG * FA_BUFSZ)  // 73728
#define NEG_BIG (-1e30f)
#define ONE_H2  0x3C003C00u              // half2(1.0, 1.0)

__global__ void __launch_bounds__(256, 2)
flash_mma(const __half* __restrict__ qkv,
          __half* __restrict__ ath,
          __half* __restrict__ atl)
{
    extern __shared__ char fsm[];
    const uint32_t sb = smem_u32(fsm);

    const int tid  = threadIdx.x;
    const int lane = tid & 31;
    const int wid  = tid >> 5;
    const int b = blockIdx.x >> 4;
    const int h = blockIdx.x & 15;
    const int yy = (int)gridDim.y - 1 - (int)blockIdx.y;   // heavy tiles first
    const int q0 = yy * FA_BQ;
    const int NT = 2 * (yy + 1);
    const int bT = b * T_DIM;
    const int hoff = h * D_DIM;

    auto load_tile = [&](int t, int bufi) {
        const int k0 = t * FA_BC;
        const int row = tid >> 2;
        const int ch2 = (tid & 3) * 2;
        const size_t rb = (size_t)(bT + k0 + row) * N_QKV + hoff;
        const uint32_t tb = sb + FA_BUF + bufi * FA_BUFSZ;
        const uint32_t d = tb + row * FA_LDB + ch2 * 16;
        const __half* skh = qkv + rb + C_DIM;
        const __half* svh = qkv + rb + 2 * C_DIM;
        cp16(d + 0 * FA_TILE,      skh + ch2 * 8);
        cp16(d + 0 * FA_TILE + 16, skh + ch2 * 8 + 8);
        cp16(d + 1 * FA_TILE,      svh + ch2 * 8);
        cp16(d + 1 * FA_TILE + 16, svh + ch2 * 8 + 8);
        CP_COMMIT();
    };

    // ---- issue Q tile load, then prefetch K/V tiles 0 & 1 ----
#pragma unroll
    for (int i = 0; i < 4; ++i) {
        int idx = tid + i * 256;          // 0..1023
        int row = idx >> 3;
        int ch  = idx & 7;
        const __half* src = qkv + (size_t)(bT + q0 + row) * N_QKV + hoff + ch * 8;
        cp16(sb + row * FA_LDB + ch * 16, src);
    }
    CP_COMMIT();
    load_tile(0, 0);
    load_tile(1, 1);          // NT >= 2 always

    CP_WAIT(2);               // Q done; K/V tiles may still be in flight
    __syncthreads();

    uint32_t qf[4][4];
#pragma unroll
    for (int ks = 0; ks < 4; ++ks) {
        uint32_t off = (uint32_t)(wid * 16 + (lane & 15)) * FA_LDB
                     + ks * 32 + (lane >> 4) * 16;
        ldsm4(qf[ks], sb + off);
    }

    float o[8][4];
#pragma unroll
    for (int i = 0; i < 8; ++i)
#pragma unroll
        for (int j = 0; j < 4; ++j) o[i][j] = 0.0f;
    float la[4] = {0.0f, 0.0f, 0.0f, 0.0f};       // l via ones-MMA
    float m0 = NEG_BIG, m1 = NEG_BIG;
    const int qr  = q0 + wid * 16;
    const int qp0 = qr + (lane >> 2);
    const int qp1 = qp0 + 8;
    const uint32_t ones[2] = {ONE_H2, ONE_H2};

    int buf = 0;
    for (int t = 0; t < NT; ++t) {
        if (t + 1 < NT) { CP_WAIT(1); } else { CP_WAIT(0); }
        __syncthreads();
        if (t + 2 < NT) {
            int nb = buf + 2; if (nb >= FA_NSTG) nb -= FA_NSTG;
            load_tile(t + 2, nb);
        }

        const int k0 = t * FA_BC;
        if (k0 <= qr + 15) {
            const uint32_t tb = sb + FA_BUF + buf * FA_BUFSZ;

            float s[8][4];
#pragma unroll
            for (int i = 0; i < 8; ++i)
#pragma unroll
                for (int j = 0; j < 4; ++j) s[i][j] = 0.0f;

#pragma unroll
            for (int ks = 0; ks < 4; ++ks) {
                uint32_t kh[4][4];
#pragma unroll
                for (int np = 0; np < 4; ++np) {
                    uint32_t off = (uint32_t)(np * 16 + (lane & 7)
                                 + ((lane >> 4) & 1) * 8) * FA_LDB
                                 + ks * 32 + ((lane >> 3) & 1) * 16;
                    ldsm4(kh[np], tb + 0 * FA_TILE + off);
                }
#pragma unroll
                for (int ni = 0; ni < 8; ++ni)
                    mma16816(s[ni], qf[ks], &kh[ni >> 1][(ni & 1) * 2]);
            }

            // causal mask (s already in log2 units)
            if (k0 + FA_BC - 1 > qr) {
#pragma unroll
                for (int ni = 0; ni < 8; ++ni) {
                    int kp = k0 + ni * 8 + 2 * (lane & 3);
                    if (kp     > qp0) s[ni][0] = NEG_BIG;
                    if (kp + 1 > qp0) s[ni][1] = NEG_BIG;
                    if (kp     > qp1) s[ni][2] = NEG_BIG;
                    if (kp + 1 > qp1) s[ni][3] = NEG_BIG;
                }
            }

            float mx0 = NEG_BIG, mx1 = NEG_BIG;
#pragma unroll
            for (int ni = 0; ni < 8; ++ni) {
                mx0 = fmaxf(mx0, fmaxf(s[ni][0], s[ni][1]));
                mx1 = fmaxf(mx1, fmaxf(s[ni][2], s[ni][3]));
            }
            mx0 = fmaxf(mx0, __shfl_xor_sync(0xffffffffu, mx0, 1));
            mx0 = fmaxf(mx0, __shfl_xor_sync(0xffffffffu, mx0, 2));
            mx1 = fmaxf(mx1, __shfl_xor_sync(0xffffffffu, mx1, 1));
            mx1 = fmaxf(mx1, __shfl_xor_sync(0xffffffffu, mx1, 2));
            const float m0n = fmaxf(m0, mx0);
            const float m1n = fmaxf(m1, mx1);
            const float c0 = fexp2(m0 - m0n);     // 0 on first tile
            const float c1 = fexp2(m1 - m1n);
            la[0] *= c0; la[2] *= c1;
#pragma unroll
            for (int ni = 0; ni < 8; ++ni) {
                o[ni][0] *= c0; o[ni][1] *= c0;
                o[ni][2] *= c1; o[ni][3] *= c1;
            }
            m0 = m0n; m1 = m1n;

            // P = exp2(s - m) as fp16 fragments; l += P @ 1; O += P V
#pragma unroll
            for (int ks = 0; ks < 4; ++ks) {
                uint32_t pa[4];
                pa[0] = ex2h2(s[2*ks][0]   - m0, s[2*ks][1]   - m0);
                pa[1] = ex2h2(s[2*ks][2]   - m1, s[2*ks][3]   - m1);
                pa[2] = ex2h2(s[2*ks+1][0] - m0, s[2*ks+1][1] - m0);
                pa[3] = ex2h2(s[2*ks+1][2] - m1, s[2*ks+1][3] - m1);

                mma16816(la, pa, ones);           // row sums

                uint32_t vh[4][4];
#pragma unroll
                for (int nd = 0; nd < 4; ++nd) {
                    uint32_t off = (uint32_t)(ks * 16 + (lane & 15)) * FA_LDB
                                 + nd * 32 + (lane >> 4) * 16;
                    ldsm4t(vh[nd], tb + 1 * FA_TILE + off);
                }
#pragma unroll
                for (int ni = 0; ni < 8; ++ni)
                    mma16816(o[ni], pa, &vh[ni >> 1][(ni & 1) * 2]);
            }
        }
        if (++buf >= FA_NSTG) buf -= FA_NSTG;
    }

    // ---- epilogue: normalize + fp16 hi/lo split store ----
    const float i0 = 1.0f / la[0];
    const float i1 = 1.0f / la[2];

    const size_t r0o = (size_t)(bT + qp0) * C_DIM + hoff + 2 * (lane & 3);
    const size_t r1o = (size_t)(bT + qp1) * C_DIM + hoff + 2 * (lane & 3);
#pragma unroll
    for (int ni = 0; ni < 8; ++ni) {
        uint32_t hh, ll;
        split2h(o[ni][0] * i0, o[ni][1] * i0, hh, ll);
        *(uint32_t*)(ath + r0o + ni * 8) = hh;
        *(uint32_t*)(atl + r0o + ni * 8) = ll;
        split2h(o[ni][2] * i1, o[ni][3] * i1, hh, ll);
        *(uint32_t*)(ath + r1o + ni * 8) = hh;
        *(uint32_t*)(atl + r1o + ni * 8) = ll;
    }
}

// ---------------------------------------------------------------------------
// Launch
// ---------------------------------------------------------------------------
extern "C" void kernel_launch(void* const* d_in, const int* in_sizes, int n_in,
                              void* d_out, int out_size)
{
    const float* x      = (const float*)d_in[0];
    const float* w_attn = (const float*)d_in[1];
    const float* b_attn = (const float*)d_in[2];
    const float* w_proj = (const float*)d_in[3];
    const float* b_proj = (const float*)d_in[4];
    float* out = (float*)d_out;

    void *p_q, *p_xh, *p_wt, *p_wpt, *p_ath, *p_atl;
    cudaGetSymbolAddress(&p_q,   g_qkvh);
    cudaGetSymbolAddress(&p_xh,  g_xh);
    cudaGetSymbolAddress(&p_wt,  g_wt);
    cudaGetSymbolAddress(&p_wpt, g_wpt);
    cudaGetSymbolAddress(&p_ath, g_ath);
    cudaGetSymbolAddress(&p_atl, g_atl);

    cudaFuncSetAttribute(gemm_qkv,
                         cudaFuncAttributeMaxDynamicSharedMemorySize, QKV_SMEM);
    cudaFuncSetAttribute(gemm_proj,
                         cudaFuncAttributeMaxDynamicSharedMemorySize, PROJ_SMEM);
    cudaFuncSetAttribute(flash_mma,
                         cudaFuncAttributeMaxDynamicSharedMemorySize, FA_SMEM);

    // 1) x -> fp16
    {
        int n = M_ROWS * C_DIM;
        k_half<<<n / 4 / 256, 256>>>(x, (__half*)p_xh, n);
    }
    // 2) transpose weights -> fp16
    {
        dim3 g(N_QKV / 32, C_DIM / 32);
        k_transpose_half<<<g, dim3(32, 8)>>>(w_attn, (__half*)p_wt, C_DIM, N_QKV);
    }
    {
        dim3 g(C_DIM / 32, C_DIM / 32);
        k_transpose_half<<<g, dim3(32, 8)>>>(w_proj, (__half*)p_wpt, C_DIM, C_DIM);
    }
    // 3) qkv = x @ w_attn + b_attn  (1-product fp16; Q scaled by log2e/8)
    {
        dim3 grid(N_QKV / 128, M_ROWS / 128);
        gemm_qkv<<<grid, 256, QKV_SMEM>>>(
            (const __half*)p_xh, (const __half*)p_wt, b_attn,
            (__half*)p_q, N_QKV, C_DIM);
    }
    // 4) causal MHA (log2-domain flash, fp16 hi/lo output)
    {
        dim3 grid(B_DIM * H_DIM, T_DIM / FA_BQ);
        flash_mma<<<grid, 256, FA_SMEM>>>((const __half*)p_q,
                                          (__half*)p_ath,
                                          (__half*)p_atl);
    }
    // 5) out = att @ w_proj + b_proj (2-product, fp32 out)
    {
        dim3 grid(C_DIM / 128, M_ROWS / 128);
        gemm_proj<<<grid, 256, PROJ_SMEM>>>(
            (const __half*)p_ath, (const __half*)p_atl, (const __half*)p_wpt,
            b_proj, out, C_DIM, C_DIM);
    }
}